// round 9
// baseline (speedup 1.0000x reference)
#include <cuda_runtime.h>
#include <cuda_bf16.h>
#include <math.h>
#include <stdint.h>

// ---------------- problem constants ----------------
#define NF      32
#define C       64
#define H       96
#define W       96
#define FEAT    2304
#define DIM     768
#define M_TOK   (NF*256)                    // 8192
#define TOK_ELEMS   (M_TOK*DIM)
#define FRAME_STRIDE (C*H*W)

__device__ __forceinline__ uint32_t f2tf32(float x){
    uint32_t r;
    asm("cvt.rna.tf32.f32 %0, %1;" : "=r"(r) : "f"(x));
    return r;
}
__device__ __forceinline__ float gelu_exact(float x){
    return 0.5f*x*(1.0f + erff(x*0.7071067811865476f));
}
__device__ __forceinline__ void mma_tf32(float* d, const uint32_t* a, const uint32_t* b){
    asm volatile(
        "mma.sync.aligned.m16n8k8.row.col.f32.tf32.tf32.f32 "
        "{%0,%1,%2,%3}, {%4,%5,%6,%7}, {%8,%9}, {%0,%1,%2,%3};"
        : "+f"(d[0]), "+f"(d[1]), "+f"(d[2]), "+f"(d[3])
        : "r"(a[0]), "r"(a[1]), "r"(a[2]), "r"(a[3]), "r"(b[0]), "r"(b[1]));
}
__device__ __forceinline__ void mma_bf16(float* d, const uint32_t* a, const uint32_t* b){
    asm volatile(
        "mma.sync.aligned.m16n8k16.row.col.f32.bf16.bf16.f32 "
        "{%0,%1,%2,%3}, {%4,%5,%6,%7}, {%8,%9}, {%0,%1,%2,%3};"
        : "+f"(d[0]), "+f"(d[1]), "+f"(d[2]), "+f"(d[3])
        : "r"(a[0]), "r"(a[1]), "r"(a[2]), "r"(a[3]), "r"(b[0]), "r"(b[1]));
}
__device__ __forceinline__ void cp16(uint32_t saddr, const void* g){
    asm volatile("cp.async.cg.shared.global [%0], [%1], 16;" :: "r"(saddr), "l"(g));
}
__device__ __forceinline__ uint32_t packbf2(__nv_bfloat16 a, __nv_bfloat16 b){
    uint32_t lo = (uint32_t)__bfloat16_as_ushort(a);
    uint32_t hi = (uint32_t)__bfloat16_as_ushort(b);
    return (hi << 16) | lo;
}
__device__ __forceinline__ void bf16split(float v, __nv_bfloat16& h, __nv_bfloat16& l){
    h = __float2bfloat16_rn(v);
    l = __float2bfloat16_rn(v - __bfloat162float(h));
}
__device__ __forceinline__ uint32_t smem_u32(const void* p){
    return (uint32_t)__cvta_generic_to_shared(p);
}
// k-permutation within aligned groups of 8: [k0,k4,k1,k5,k2,k6,k3,k7]
// -> tf32 fragment pair (k, k+4) becomes adjacent (one LDS.64).
__device__ __forceinline__ int kperm(int k){
    int p = k & 7;
    return (k & ~7) | ((p < 4) ? (p*2) : ((p-4)*2 + 1));
}

// ---------------- device globals ----------------
__device__ unsigned long long g_wb64[9*4*8*64]; // conv w [tap][cg][ci-pair][co]: lo32=hi-pair, hi32=lo-pair
__device__ float g_bnscale[64];
__device__ float g_bnshift[64];
__device__ float g_w32[DIM*FEAT];               // proj_w tf32 bits, k-permuted
__device__ float g_a32[(long)M_TOK*FEAT];       // masked patches tf32 bits, k-permuted

// =====================================================================
// Kernel 0: conv-weight bf16-split u64 repack + BN fold + proj_w tf32
// (k-permuted) pre-convert
// =====================================================================
__global__ void prep_kernel(const float* __restrict__ cw,
                            const float* __restrict__ cb,
                            const float* __restrict__ gamma,
                            const float* __restrict__ beta,
                            const float* __restrict__ mean,
                            const float* __restrict__ var,
                            const float* __restrict__ pw)
{
    int idx = blockIdx.x*256 + threadIdx.x;
    if (idx < 9*4*8*64){
        int co  = idx & 63;
        int c   = (idx >> 6) & 7;
        int cg  = (idx >> 9) & 3;
        int tap = idx >> 11;
        int ci0 = cg*16 + 2*c;
        float w0 = cw[(co*64 + ci0)*9 + tap];
        float w1 = cw[(co*64 + ci0 + 1)*9 + tap];
        __nv_bfloat16 h0, l0, h1, l1;
        bf16split(w0, h0, l0);
        bf16split(w1, h1, l1);
        g_wb64[idx] = ((unsigned long long)packbf2(l0, l1) << 32)
                    |  (unsigned long long)packbf2(h0, h1);
    }
    if (idx < DIM*FEAT){
        int d = idx / FEAT, k = idx - d*FEAT;
        g_w32[(long)d*FEAT + kperm(k)] = __uint_as_float(f2tf32(pw[idx]));
    }
    if (blockIdx.x == 0 && threadIdx.x < 64){
        int co = threadIdx.x;
        float s = gamma[co] * rsqrtf(var[co] + 1e-5f);
        g_bnscale[co] = s;
        g_bnshift[co] = (cb[co] - mean[co]) * s + beta[co];
    }
}

// =====================================================================
// Kernel 1: conv3x3 implicit GEMM, 3xBF16 legacy mma.
// Per ci-chunk(16): cp.async all 9 taps of B (u64 hi/lo packed) overlapped
// with halo stage; then 9 taps of mma with NO barriers (2 barriers/cg).
// LDS.64 yields {hi,lo} fragment pairs in one instruction.
// =====================================================================
#define CV_SX_U64 1600            // 8 ci-pairs x 10 y x 20 x
#define CV_SB_U64 (9*8*68)        // 9 taps x 8 ci-pairs x 64 co (pad 68)
#define CV_SMEM_BYTES ((CV_SX_U64 + CV_SB_U64)*8)   // 51,968

__global__ __launch_bounds__(256, 2) void conv_mma_kernel(
    const float* __restrict__ x,
    const float* __restrict__ mask,
    float* __restrict__ out_patches)
{
    extern __shared__ __align__(16) unsigned long long dynsm[];
    unsigned long long* s_x = dynsm;                 // [c][y][x] : c*200 + y*20 + x
    unsigned long long* s_b = dynsm + CV_SX_U64;     // [tap][c][co] : (tap*8+c)*68 + co

    __shared__ float s_mask[36];
    __shared__ float s_scale[64], s_shift[64];

    const int tid  = threadIdx.x;
    const int lane = tid & 31;
    const int wid  = tid >> 5;
    const int wm   = wid & 3;
    const int wn   = wid >> 2;
    const int lg   = lane >> 2;      // 0..7
    const int lt   = lane & 3;       // 0..3

    const int w0    = blockIdx.x * 16;
    const int h0    = blockIdx.y * 8;
    const int frame = blockIdx.z;
    const float* xf = x + (long)frame * FRAME_STRIDE;

    if (tid < 36) s_mask[tid] = mask[tid];
    if (tid < 64){ s_scale[tid] = g_bnscale[tid]; s_shift[tid] = g_bnshift[tid]; }

    float acc[2][4][4];
    #pragma unroll
    for (int mt=0;mt<2;mt++)
        #pragma unroll
        for (int nt=0;nt<4;nt++)
            #pragma unroll
            for (int r=0;r<4;r++) acc[mt][nt][r] = 0.f;

    const int bc  = tid >> 5;        // staging: ci-pair 0..7
    const int bch = tid & 31;        // staging: co-pair-chunk 0..31

    for (int cg = 0; cg < 4; cg++){
        __syncthreads();   // previous cg's reads of s_x/s_b complete

        // ---- issue cp.async for ALL 9 taps of B for this cg ----
        #pragma unroll
        for (int j = 0; j < 9; j++){
            uint32_t dst = smem_u32(s_b + ((j*8 + bc)*68 + 2*bch));
            cp16(dst, g_wb64 + (((long)(j*4 + cg)*8 + bc)*64 + 2*bch));
        }
        asm volatile("cp.async.commit_group;" ::: "memory");

        // ---- halo stage (LDG + bf16 split + STS.64), overlaps cp.async ----
        for (int i = tid; i < 1600; i += 256){
            int c  = i / 200;
            int r2 = i - c*200;
            int yy = r2 / 20;
            int xx = r2 - yy*20;
            int gy = h0 + yy - 1, gx = w0 + xx - 1;
            float v0 = 0.f, v1 = 0.f;
            if (gy >= 0 && gy < H && gx >= 0 && gx < W){
                long base = (long)(cg*16 + 2*c)*(H*W) + gy*W + gx;
                v0 = xf[base];
                v1 = xf[base + H*W];
            }
            __nv_bfloat16 h0b, l0b, h1b, l1b;
            bf16split(v0, h0b, l0b);
            bf16split(v1, h1b, l1b);
            s_x[i] = ((unsigned long long)packbf2(l0b, l1b) << 32)
                   |  (unsigned long long)packbf2(h0b, h1b);
        }
        asm volatile("cp.async.wait_group 0;" ::: "memory");
        __syncthreads();

        // ---- 9 taps, no barriers ----
        #pragma unroll
        for (int tap = 0; tap < 9; tap++){
            const int ky = tap / 3, kx = tap - ky*3;
            uint32_t ah[2][4], al[2][4], bh[4][2], bl[4][2];
            #pragma unroll
            for (int mt = 0; mt < 2; mt++){
                const int py = wm*2 + mt + ky;
                const int px = lg + kx;
                const int base0 = lt*200     + py*20 + px;
                const int base1 = (lt+4)*200 + py*20 + px;
                uint2 a0 = *(const uint2*)&s_x[base0];
                uint2 a1 = *(const uint2*)&s_x[base0 + 8];
                uint2 a2 = *(const uint2*)&s_x[base1];
                uint2 a3 = *(const uint2*)&s_x[base1 + 8];
                ah[mt][0]=a0.x; al[mt][0]=a0.y;
                ah[mt][1]=a1.x; al[mt][1]=a1.y;
                ah[mt][2]=a2.x; al[mt][2]=a2.y;
                ah[mt][3]=a3.x; al[mt][3]=a3.y;
            }
            #pragma unroll
            for (int nt = 0; nt < 4; nt++){
                const int co = wn*32 + nt*8 + lg;
                uint2 b0 = *(const uint2*)&s_b[(tap*8 + lt  )*68 + co];
                uint2 b1 = *(const uint2*)&s_b[(tap*8 + lt+4)*68 + co];
                bh[nt][0]=b0.x; bl[nt][0]=b0.y;
                bh[nt][1]=b1.x; bl[nt][1]=b1.y;
            }
            #pragma unroll
            for (int mt = 0; mt < 2; mt++)
                #pragma unroll
                for (int nt = 0; nt < 4; nt++){
                    mma_bf16(acc[mt][nt], ah[mt], bh[nt]);
                    mma_bf16(acc[mt][nt], ah[mt], bl[nt]);
                    mma_bf16(acc[mt][nt], al[mt], bh[nt]);
                }
        }
    }

    // ---- epilogue: BN + GELU + mask -> patches + k-permuted tf32 copy ----
    #pragma unroll
    for (int mt = 0; mt < 2; mt++){
        const int r0 = wm*32 + mt*16 + lg;
        #pragma unroll
        for (int dr = 0; dr < 2; dr++){
            const int r = r0 + dr*8;
            const int hh = h0 + (r >> 4);
            const int ww = w0 + (r & 15);
            const int l = hh / 6, i_in = hh - l*6;
            const int rr = ww / 6, j_in = ww - rr*6;
            const float mk = s_mask[i_in*6 + j_in];
            const long arow = ((long)frame*256 + l*16 + rr)*FEAT;
            #pragma unroll
            for (int nt = 0; nt < 4; nt++){
                const int c0 = wn*32 + nt*8 + (lt << 1);
                #pragma unroll
                for (int dc = 0; dc < 2; dc++){
                    const int co = c0 + dc;
                    const float v = acc[mt][nt][dr*2 + dc];
                    float o = gelu_exact(v*s_scale[co] + s_shift[co]) * mk;
                    const int k = co*36 + i_in*6 + j_in;
                    out_patches[arow + k] = o;
                    g_a32[arow + kperm(k)] = __uint_as_float(f2tf32(o));
                }
            }
        }
    }
}

// =====================================================================
// Kernel 2: tokens = gelu(A @ Wp^T + bias), tf32 mma + cp.async pipeline.
// k-permuted operands -> each fragment (k,k+4) pair is one LDS.64.
// =====================================================================
#define GBM 128
#define GBN 64
#define GBK 32
#define KSTR 36
#define STAGES 3
#define SA_WORDS (GBM*KSTR)
#define SB_WORDS (GBN*KSTR)
#define GEMM_SMEM_BYTES ((STAGES*(SA_WORDS+SB_WORDS))*4)   // 82944

__global__ __launch_bounds__(256, 2) void gemm_tokens_cp_kernel(
    const float* __restrict__ bias,
    float* __restrict__ tok)
{
    extern __shared__ uint32_t smdyn[];
    uint32_t* s_a = smdyn;
    uint32_t* s_b = smdyn + STAGES*SA_WORDS;
    const uint32_t sa_base = smem_u32(s_a);
    const uint32_t sb_base = smem_u32(s_b);

    const int tid  = threadIdx.x;
    const int lane = tid & 31;
    const int wid  = tid >> 5;
    const int wm   = wid & 3;
    const int wn   = wid >> 2;
    const int lg   = lane >> 2;
    const int lt   = lane & 3;
    const int bm   = blockIdx.y;
    const int bn   = blockIdx.x;

    const float* Ab = g_a32 + (long)bm*GBM*FEAT;
    const float* Bb = g_w32 + (long)bn*GBN*FEAT;

    float acc[2][4][4];
    #pragma unroll
    for (int mt=0;mt<2;mt++)
        #pragma unroll
        for (int nt=0;nt<4;nt++)
            #pragma unroll
            for (int r=0;r<4;r++) acc[mt][nt][r] = 0.f;

    const int crowA = tid >> 3;
    const int ck4   = (tid & 7) << 2;

    #pragma unroll
    for (int st = 0; st < 2; st++){
        const int kg = st*GBK;
        #pragma unroll
        for (int j = 0; j < 4; j++){
            int row = crowA + j*32;
            cp16(sa_base + (uint32_t)((st*GBM + row)*KSTR + ck4)*4,
                 Ab + (long)row*FEAT + kg + ck4);
        }
        #pragma unroll
        for (int j = 0; j < 2; j++){
            int row = crowA + j*32;
            if (row < GBN)
                cp16(sb_base + (uint32_t)((st*GBN + row)*KSTR + ck4)*4,
                     Bb + (long)row*FEAT + kg + ck4);
        }
        asm volatile("cp.async.commit_group;");
    }
    asm volatile("cp.async.wait_group 1;");
    __syncthreads();

    const int NKT = FEAT / GBK;   // 72
    for (int kt = 0; kt < NKT; kt++){
        const int cur = kt % STAGES;
        if (kt + 2 < NKT){
            const int st = (kt + 2) % STAGES;
            const int kg = (kt + 2)*GBK;
            #pragma unroll
            for (int j = 0; j < 4; j++){
                int row = crowA + j*32;
                cp16(sa_base + (uint32_t)((st*GBM + row)*KSTR + ck4)*4,
                     Ab + (long)row*FEAT + kg + ck4);
            }
            #pragma unroll
            for (int j = 0; j < 2; j++){
                int row = crowA + j*32;
                if (row < GBN)
                    cp16(sb_base + (uint32_t)((st*GBN + row)*KSTR + ck4)*4,
                         Bb + (long)row*FEAT + kg + ck4);
            }
        }
        asm volatile("cp.async.commit_group;");

        const uint32_t* pa = s_a + cur*SA_WORDS;
        const uint32_t* pb = s_b + cur*SB_WORDS;
        #pragma unroll
        for (int ks = 0; ks < 4; ks++){
            uint32_t af[2][4], bf[4][2];
            const int koff = ks*8 + lt*2;     // permuted pair position
            #pragma unroll
            for (int mt=0;mt<2;mt++){
                int r0 = wm*32 + mt*16 + lg;
                uint2 v0 = *(const uint2*)(pa + r0*KSTR + koff);
                uint2 v1 = *(const uint2*)(pa + (r0+8)*KSTR + koff);
                af[mt][0] = v0.x;   // k = kb
                af[mt][2] = v0.y;   // k = kb+4
                af[mt][1] = v1.x;
                af[mt][3] = v1.y;
            }
            #pragma unroll
            for (int nt=0;nt<4;nt++){
                int c0 = wn*32 + nt*8 + lg;
                uint2 v = *(const uint2*)(pb + c0*KSTR + koff);
                bf[nt][0] = v.x;
                bf[nt][1] = v.y;
            }
            #pragma unroll
            for (int mt=0;mt<2;mt++)
                #pragma unroll
                for (int nt=0;nt<4;nt++)
                    mma_tf32(acc[mt][nt], af[mt], bf[nt]);
        }

        asm volatile("cp.async.wait_group 1;");
        __syncthreads();
    }

    #pragma unroll
    for (int mt=0;mt<2;mt++){
        const int r0 = bm*GBM + wm*32 + mt*16 + lg;
        #pragma unroll
        for (int nt=0;nt<4;nt++){
            const int c0 = bn*GBN + wn*32 + nt*8 + (lt << 1);
            float2 b2 = *(const float2*)(bias + c0);
            float2 o0, o1;
            o0.x = gelu_exact(acc[mt][nt][0] + b2.x);
            o0.y = gelu_exact(acc[mt][nt][1] + b2.y);
            o1.x = gelu_exact(acc[mt][nt][2] + b2.x);
            o1.y = gelu_exact(acc[mt][nt][3] + b2.y);
            *(float2*)(tok + (long)r0*DIM + c0)     = o0;
            *(float2*)(tok + (long)(r0+8)*DIM + c0) = o1;
        }
    }
}

// =====================================================================
extern "C" void kernel_launch(void* const* d_in, const int* in_sizes, int n_in,
                              void* d_out, int out_size)
{
    const float* x      = (const float*)d_in[0];
    const float* conv_w = (const float*)d_in[1];
    const float* conv_b = (const float*)d_in[2];
    const float* gamma  = (const float*)d_in[3];
    const float* beta   = (const float*)d_in[4];
    const float* mean   = (const float*)d_in[5];
    const float* var    = (const float*)d_in[6];
    const float* proj_w = (const float*)d_in[7];
    const float* proj_b = (const float*)d_in[8];
    const float* mask   = (const float*)d_in[9];

    float* tokens  = (float*)d_out;                 // [8192, 768]
    float* patches = (float*)d_out + TOK_ELEMS;     // [8192, 2304]

    cudaFuncSetAttribute(conv_mma_kernel,
                         cudaFuncAttributeMaxDynamicSharedMemorySize,
                         CV_SMEM_BYTES);
    cudaFuncSetAttribute(gemm_tokens_cp_kernel,
                         cudaFuncAttributeMaxDynamicSharedMemorySize,
                         GEMM_SMEM_BYTES);

    // 0) weight repack (bf16 split u64) + BN fold + proj_w tf32 (permuted)
    prep_kernel<<<(DIM*FEAT + 255)/256, 256>>>(conv_w, conv_b, gamma, beta,
                                               mean, var, proj_w);

    // 1) conv as implicit GEMM (3xBF16) -> patches + permuted tf32 A copy
    {
        dim3 grid(W/16, H/8, NF);
        conv_mma_kernel<<<grid, 256, CV_SMEM_BYTES>>>(x, mask, patches);
    }

    // 2) projection GEMM + bias + GELU (cp.async pipelined tf32 mma)
    {
        dim3 grid(DIM/GBN, M_TOK/GBM);
        gemm_tokens_cp_kernel<<<grid, 256, GEMM_SMEM_BYTES>>>(proj_b, tokens);
    }
}

// round 10
// speedup vs baseline: 1.2395x; 1.2395x over previous
#include <cuda_runtime.h>
#include <cuda_bf16.h>
#include <math.h>
#include <stdint.h>

// ---------------- problem constants ----------------
#define NF      32
#define C       64
#define H       96
#define W       96
#define FEAT    2304
#define DIM     768
#define M_TOK   (NF*256)                    // 8192
#define TOK_ELEMS   (M_TOK*DIM)
#define FRAME_STRIDE (C*H*W)

__device__ __forceinline__ uint32_t f2tf32(float x){
    uint32_t r;
    asm("cvt.rna.tf32.f32 %0, %1;" : "=r"(r) : "f"(x));
    return r;
}
__device__ __forceinline__ float gelu_exact(float x){
    return 0.5f*x*(1.0f + erff(x*0.7071067811865476f));
}
__device__ __forceinline__ void mma_tf32(float* d, const uint32_t* a, const uint32_t* b){
    asm volatile(
        "mma.sync.aligned.m16n8k8.row.col.f32.tf32.tf32.f32 "
        "{%0,%1,%2,%3}, {%4,%5,%6,%7}, {%8,%9}, {%0,%1,%2,%3};"
        : "+f"(d[0]), "+f"(d[1]), "+f"(d[2]), "+f"(d[3])
        : "r"(a[0]), "r"(a[1]), "r"(a[2]), "r"(a[3]), "r"(b[0]), "r"(b[1]));
}
__device__ __forceinline__ void mma_bf16(float* d, const uint32_t* a, const uint32_t* b){
    asm volatile(
        "mma.sync.aligned.m16n8k16.row.col.f32.bf16.bf16.f32 "
        "{%0,%1,%2,%3}, {%4,%5,%6,%7}, {%8,%9}, {%0,%1,%2,%3};"
        : "+f"(d[0]), "+f"(d[1]), "+f"(d[2]), "+f"(d[3])
        : "r"(a[0]), "r"(a[1]), "r"(a[2]), "r"(a[3]), "r"(b[0]), "r"(b[1]));
}
__device__ __forceinline__ void cp16(uint32_t saddr, const void* g){
    asm volatile("cp.async.cg.shared.global [%0], [%1], 16;" :: "r"(saddr), "l"(g));
}
__device__ __forceinline__ uint32_t packbf2(__nv_bfloat16 a, __nv_bfloat16 b){
    uint32_t lo = (uint32_t)__bfloat16_as_ushort(a);
    uint32_t hi = (uint32_t)__bfloat16_as_ushort(b);
    return (hi << 16) | lo;
}
__device__ __forceinline__ void bf16split(float v, __nv_bfloat16& h, __nv_bfloat16& l){
    h = __float2bfloat16_rn(v);
    l = __float2bfloat16_rn(v - __bfloat162float(h));
}
__device__ __forceinline__ uint32_t smem_u32(const void* p){
    return (uint32_t)__cvta_generic_to_shared(p);
}

// ---------------- device globals ----------------
__device__ uint32_t g_wbh[9*4*8*64];     // conv weights bf16x2 hi [tap][cg][ci-pair][co]
__device__ uint32_t g_wbl[9*4*8*64];     // bf16x2 lo residual
__device__ float g_bnscale[64];
__device__ float g_bnshift[64];
__device__ float g_w32[DIM*FEAT];        // proj_w tf32 bits
__device__ float g_a32[(long)M_TOK*FEAT];// masked patches tf32 bits

// =====================================================================
// Kernel 0: conv-weight bf16-split repack + BN fold + proj_w tf32 convert
// (identical arithmetic to round 6)
// =====================================================================
__global__ void prep_kernel(const float* __restrict__ cw,
                            const float* __restrict__ cb,
                            const float* __restrict__ gamma,
                            const float* __restrict__ beta,
                            const float* __restrict__ mean,
                            const float* __restrict__ var,
                            const float* __restrict__ pw)
{
    int idx = blockIdx.x*256 + threadIdx.x;
    if (idx < 9*4*8*64){
        int co  = idx & 63;
        int c   = (idx >> 6) & 7;
        int cg  = (idx >> 9) & 3;
        int tap = idx >> 11;
        int ci0 = cg*16 + 2*c;
        float w0 = cw[(co*64 + ci0)*9 + tap];
        float w1 = cw[(co*64 + ci0 + 1)*9 + tap];
        __nv_bfloat16 h0, l0, h1, l1;
        bf16split(w0, h0, l0);
        bf16split(w1, h1, l1);
        g_wbh[idx] = packbf2(h0, h1);
        g_wbl[idx] = packbf2(l0, l1);
    }
    if (idx < DIM*FEAT)
        g_w32[idx] = __uint_as_float(f2tf32(pw[idx]));
    if (blockIdx.x == 0 && threadIdx.x < 64){
        int co = threadIdx.x;
        float s = gamma[co] * rsqrtf(var[co] + 1e-5f);
        g_bnscale[co] = s;
        g_bnshift[co] = (cb[co] - mean[co]) * s + beta[co];
    }
}

// =====================================================================
// Kernel 1: conv3x3 implicit GEMM, 3xBF16 legacy mma.
// Round-6 fragment layouts (measured conflict-free) + whole-cg B
// prestaging via cp.async: 2 barriers per ci-chunk, 9-tap loop barrier-
// and prefetch-free.
// smem (u32): s_xh[1600] s_xl[1600] s_bh[9*8*72] s_bl[9*8*72] = 54,272 B
// =====================================================================
#define CV_SX 1600                 // 8 ci-pairs x 10 y x 20 x (stride 200)
#define CV_SB (9*8*72)             // 9 taps x 8 ci-pairs x co (pad 72)
#define CV_SMEM_BYTES ((2*CV_SX + 2*CV_SB)*4)

__global__ __launch_bounds__(256, 2) void conv_mma_kernel(
    const float* __restrict__ x,
    const float* __restrict__ mask,
    float* __restrict__ out_patches)
{
    extern __shared__ __align__(16) uint32_t dynsm[];
    uint32_t* s_xh = dynsm;                    // [c][y][x] : c*200+y*20+x
    uint32_t* s_xl = dynsm + CV_SX;
    uint32_t* s_bh = dynsm + 2*CV_SX;          // [tap][c][co] : (tap*8+c)*72+co
    uint32_t* s_bl = dynsm + 2*CV_SX + CV_SB;

    __shared__ float s_mask[36];
    __shared__ float s_scale[64], s_shift[64];

    const int tid  = threadIdx.x;
    const int lane = tid & 31;
    const int wid  = tid >> 5;
    const int wm   = wid & 3;
    const int wn   = wid >> 2;
    const int lg   = lane >> 2;      // 0..7
    const int lt   = lane & 3;       // 0..3

    const int w0    = blockIdx.x * 16;
    const int h0    = blockIdx.y * 8;
    const int frame = blockIdx.z;
    const float* xf = x + (long)frame * FRAME_STRIDE;

    if (tid < 36) s_mask[tid] = mask[tid];
    if (tid < 64){ s_scale[tid] = g_bnscale[tid]; s_shift[tid] = g_bnshift[tid]; }

    float acc[2][4][4];
    #pragma unroll
    for (int mt=0;mt<2;mt++)
        #pragma unroll
        for (int nt=0;nt<4;nt++)
            #pragma unroll
            for (int r=0;r<4;r++) acc[mt][nt][r] = 0.f;

    for (int cg = 0; cg < 4; cg++){
        __syncthreads();   // previous cg's reads of s_x*/s_b* complete

        // ---- cp.async: all 9 taps of B (hi & lo) for this cg ----
        // 1152 16B-chunks per array; chunk i -> tap=i>>7, c=(i>>4)&7, q=i&15
        for (int i = tid; i < 1152; i += 256){
            int q = i & 15;
            int c = (i >> 4) & 7;
            int j = i >> 7;
            uint32_t soff = (uint32_t)(((j*8 + c)*72 + q*4) * 4);
            long goff = ((long)(j*4 + cg)*8 + c)*64 + q*4;
            cp16(smem_u32(s_bh) + soff, g_wbh + goff);
            cp16(smem_u32(s_bl) + soff, g_wbl + goff);
        }
        asm volatile("cp.async.commit_group;" ::: "memory");

        // ---- halo stage (LDG + bf16 split + STS), overlaps cp.async ----
        for (int i = tid; i < 1600; i += 256){
            int c  = i / 200;
            int r2 = i - c*200;
            int yy = r2 / 20;
            int xx = r2 - yy*20;
            int gy = h0 + yy - 1, gx = w0 + xx - 1;
            float v0 = 0.f, v1 = 0.f;
            if (gy >= 0 && gy < H && gx >= 0 && gx < W){
                long base = (long)(cg*16 + 2*c)*(H*W) + gy*W + gx;
                v0 = xf[base];
                v1 = xf[base + H*W];
            }
            __nv_bfloat16 h0b, l0b, h1b, l1b;
            bf16split(v0, h0b, l0b);
            bf16split(v1, h1b, l1b);
            s_xh[i] = packbf2(h0b, h1b);
            s_xl[i] = packbf2(l0b, l1b);
        }
        asm volatile("cp.async.wait_group 0;" ::: "memory");
        __syncthreads();

        // ---- 9 taps, no barriers, no prefetch bookkeeping ----
        #pragma unroll
        for (int tap = 0; tap < 9; tap++){
            const int ky = tap / 3, kx = tap - ky*3;
            uint32_t ah[2][4], al[2][4], bh[4][2], bl[4][2];
            #pragma unroll
            for (int mt = 0; mt < 2; mt++){
                const int py = wm*2 + mt + ky;
                const int px = lg + kx;
                const int b0 = lt*200     + py*20 + px;
                const int b1 = (lt+4)*200 + py*20 + px;
                ah[mt][0] = s_xh[b0];
                ah[mt][1] = s_xh[b0 + 8];
                ah[mt][2] = s_xh[b1];
                ah[mt][3] = s_xh[b1 + 8];
                al[mt][0] = s_xl[b0];
                al[mt][1] = s_xl[b0 + 8];
                al[mt][2] = s_xl[b1];
                al[mt][3] = s_xl[b1 + 8];
            }
            #pragma unroll
            for (int nt = 0; nt < 4; nt++){
                const int co = wn*32 + nt*8 + lg;
                bh[nt][0] = s_bh[(tap*8 + lt  )*72 + co];
                bh[nt][1] = s_bh[(tap*8 + lt+4)*72 + co];
                bl[nt][0] = s_bl[(tap*8 + lt  )*72 + co];
                bl[nt][1] = s_bl[(tap*8 + lt+4)*72 + co];
            }
            #pragma unroll
            for (int mt = 0; mt < 2; mt++)
                #pragma unroll
                for (int nt = 0; nt < 4; nt++){
                    mma_bf16(acc[mt][nt], ah[mt], bh[nt]);
                    mma_bf16(acc[mt][nt], ah[mt], bl[nt]);
                    mma_bf16(acc[mt][nt], al[mt], bh[nt]);
                }
        }
    }

    // ---- epilogue: BN + GELU + mask -> patches + tf32 copy ----
    #pragma unroll
    for (int mt = 0; mt < 2; mt++){
        const int r0 = wm*32 + mt*16 + lg;
        #pragma unroll
        for (int dr = 0; dr < 2; dr++){
            const int r = r0 + dr*8;
            const int hh = h0 + (r >> 4);
            const int ww = w0 + (r & 15);
            const int l = hh / 6, i_in = hh - l*6;
            const int rr = ww / 6, j_in = ww - rr*6;
            const float mk = s_mask[i_in*6 + j_in];
            const long arow = ((long)frame*256 + l*16 + rr)*FEAT;
            #pragma unroll
            for (int nt = 0; nt < 4; nt++){
                const int c0 = wn*32 + nt*8 + (lt << 1);
                #pragma unroll
                for (int dc = 0; dc < 2; dc++){
                    const int co = c0 + dc;
                    const float v = acc[mt][nt][dr*2 + dc];
                    float o = gelu_exact(v*s_scale[co] + s_shift[co]) * mk;
                    const long k = arow + co*36 + i_in*6 + j_in;
                    out_patches[k] = o;
                    g_a32[k] = __uint_as_float(f2tf32(o));
                }
            }
        }
    }
}

// =====================================================================
// Kernel 2: tokens = gelu(A @ Wp^T + bias), tf32 mma + cp.async pipeline
// (round-5/6 kernel, known good, unchanged)
// =====================================================================
#define GBM 128
#define GBN 64
#define GBK 32
#define KSTR 36
#define STAGES 3
#define SA_WORDS (GBM*KSTR)
#define SB_WORDS (GBN*KSTR)
#define GEMM_SMEM_BYTES ((STAGES*(SA_WORDS+SB_WORDS))*4)   // 82944

__global__ __launch_bounds__(256, 2) void gemm_tokens_cp_kernel(
    const float* __restrict__ bias,
    float* __restrict__ tok)
{
    extern __shared__ uint32_t smdyn[];
    uint32_t* s_a = smdyn;
    uint32_t* s_b = smdyn + STAGES*SA_WORDS;
    const uint32_t sa_base = smem_u32(s_a);
    const uint32_t sb_base = smem_u32(s_b);

    const int tid  = threadIdx.x;
    const int lane = tid & 31;
    const int wid  = tid >> 5;
    const int wm   = wid & 3;
    const int wn   = wid >> 2;
    const int bm   = blockIdx.y;
    const int bn   = blockIdx.x;

    const float* Ab = g_a32 + (long)bm*GBM*FEAT;
    const float* Bb = g_w32 + (long)bn*GBN*FEAT;

    float acc[2][4][4];
    #pragma unroll
    for (int mt=0;mt<2;mt++)
        #pragma unroll
        for (int nt=0;nt<4;nt++)
            #pragma unroll
            for (int r=0;r<4;r++) acc[mt][nt][r] = 0.f;

    const int crowA = tid >> 3;
    const int ck4   = (tid & 7) << 2;

    #pragma unroll
    for (int st = 0; st < 2; st++){
        const int kg = st*GBK;
        #pragma unroll
        for (int j = 0; j < 4; j++){
            int row = crowA + j*32;
            cp16(sa_base + (uint32_t)((st*GBM + row)*KSTR + ck4)*4,
                 Ab + (long)row*FEAT + kg + ck4);
        }
        #pragma unroll
        for (int j = 0; j < 2; j++){
            int row = crowA + j*32;
            if (row < GBN)
                cp16(sb_base + (uint32_t)((st*GBN + row)*KSTR + ck4)*4,
                     Bb + (long)row*FEAT + kg + ck4);
        }
        asm volatile("cp.async.commit_group;");
    }
    asm volatile("cp.async.wait_group 1;");
    __syncthreads();

    const int NKT = FEAT / GBK;   // 72
    for (int kt = 0; kt < NKT; kt++){
        const int cur = kt % STAGES;
        if (kt + 2 < NKT){
            const int st = (kt + 2) % STAGES;
            const int kg = (kt + 2)*GBK;
            #pragma unroll
            for (int j = 0; j < 4; j++){
                int row = crowA + j*32;
                cp16(sa_base + (uint32_t)((st*GBM + row)*KSTR + ck4)*4,
                     Ab + (long)row*FEAT + kg + ck4);
            }
            #pragma unroll
            for (int j = 0; j < 2; j++){
                int row = crowA + j*32;
                if (row < GBN)
                    cp16(sb_base + (uint32_t)((st*GBN + row)*KSTR + ck4)*4,
                         Bb + (long)row*FEAT + kg + ck4);
            }
        }
        asm volatile("cp.async.commit_group;");

        const uint32_t* pa = s_a + cur*SA_WORDS;
        const uint32_t* pb = s_b + cur*SB_WORDS;
        #pragma unroll
        for (int ks = 0; ks < 4; ks++){
            const int kb = ks*8 + (lane & 3);
            uint32_t af[2][4], bf[4][2];
            #pragma unroll
            for (int mt=0;mt<2;mt++){
                int r0 = wm*32 + mt*16 + (lane >> 2);
                af[mt][0] = pa[r0*KSTR + kb];
                af[mt][1] = pa[(r0+8)*KSTR + kb];
                af[mt][2] = pa[r0*KSTR + kb + 4];
                af[mt][3] = pa[(r0+8)*KSTR + kb + 4];
            }
            #pragma unroll
            for (int nt=0;nt<4;nt++){
                int c0 = wn*32 + nt*8 + (lane >> 2);
                bf[nt][0] = pb[c0*KSTR + kb];
                bf[nt][1] = pb[c0*KSTR + kb + 4];
            }
            #pragma unroll
            for (int mt=0;mt<2;mt++)
                #pragma unroll
                for (int nt=0;nt<4;nt++)
                    mma_tf32(acc[mt][nt], af[mt], bf[nt]);
        }

        asm volatile("cp.async.wait_group 1;");
        __syncthreads();
    }

    #pragma unroll
    for (int mt=0;mt<2;mt++){
        const int r0 = bm*GBM + wm*32 + mt*16 + (lane >> 2);
        #pragma unroll
        for (int nt=0;nt<4;nt++){
            const int c0 = bn*GBN + wn*32 + nt*8 + ((lane & 3) << 1);
            float2 b2 = *(const float2*)(bias + c0);
            float2 o0, o1;
            o0.x = gelu_exact(acc[mt][nt][0] + b2.x);
            o0.y = gelu_exact(acc[mt][nt][1] + b2.y);
            o1.x = gelu_exact(acc[mt][nt][2] + b2.x);
            o1.y = gelu_exact(acc[mt][nt][3] + b2.y);
            *(float2*)(tok + (long)r0*DIM + c0)     = o0;
            *(float2*)(tok + (long)(r0+8)*DIM + c0) = o1;
        }
    }
}

// =====================================================================
extern "C" void kernel_launch(void* const* d_in, const int* in_sizes, int n_in,
                              void* d_out, int out_size)
{
    const float* x      = (const float*)d_in[0];
    const float* conv_w = (const float*)d_in[1];
    const float* conv_b = (const float*)d_in[2];
    const float* gamma  = (const float*)d_in[3];
    const float* beta   = (const float*)d_in[4];
    const float* mean   = (const float*)d_in[5];
    const float* var    = (const float*)d_in[6];
    const float* proj_w = (const float*)d_in[7];
    const float* proj_b = (const float*)d_in[8];
    const float* mask   = (const float*)d_in[9];

    float* tokens  = (float*)d_out;                 // [8192, 768]
    float* patches = (float*)d_out + TOK_ELEMS;     // [8192, 2304]

    cudaFuncSetAttribute(conv_mma_kernel,
                         cudaFuncAttributeMaxDynamicSharedMemorySize,
                         CV_SMEM_BYTES);
    cudaFuncSetAttribute(gemm_tokens_cp_kernel,
                         cudaFuncAttributeMaxDynamicSharedMemorySize,
                         GEMM_SMEM_BYTES);

    // 0) weight repack (bf16 split) + BN fold + proj_w tf32 convert
    prep_kernel<<<(DIM*FEAT + 255)/256, 256>>>(conv_w, conv_b, gamma, beta,
                                               mean, var, proj_w);

    // 1) conv as implicit GEMM (3xBF16) -> patches + tf32 A copy
    {
        dim3 grid(W/16, H/8, NF);
        conv_mma_kernel<<<grid, 256, CV_SMEM_BYTES>>>(x, mask, patches);
    }

    // 2) projection GEMM + bias + GELU (cp.async pipelined tf32 mma)
    {
        dim3 grid(DIM/GBN, M_TOK/GBM);
        gemm_tokens_cp_kernel<<<grid, 256, GEMM_SMEM_BYTES>>>(proj_b, tokens);
    }
}

// round 11
// speedup vs baseline: 1.3108x; 1.0575x over previous
#include <cuda_runtime.h>
#include <cuda_bf16.h>
#include <cuda_fp16.h>
#include <math.h>
#include <stdint.h>

// ---------------- problem constants ----------------
#define NF      32
#define C       64
#define H       96
#define W       96
#define FEAT    2304
#define DIM     768
#define M_TOK   (NF*256)                    // 8192
#define TOK_ELEMS   (M_TOK*DIM)
#define FRAME_STRIDE (C*H*W)

__device__ __forceinline__ uint32_t f2tf32(float x){
    uint32_t r;
    asm("cvt.rna.tf32.f32 %0, %1;" : "=r"(r) : "f"(x));
    return r;
}
__device__ __forceinline__ float gelu_exact(float x){
    return 0.5f*x*(1.0f + erff(x*0.7071067811865476f));
}
__device__ __forceinline__ void mma_tf32(float* d, const uint32_t* a, const uint32_t* b){
    asm volatile(
        "mma.sync.aligned.m16n8k8.row.col.f32.tf32.tf32.f32 "
        "{%0,%1,%2,%3}, {%4,%5,%6,%7}, {%8,%9}, {%0,%1,%2,%3};"
        : "+f"(d[0]), "+f"(d[1]), "+f"(d[2]), "+f"(d[3])
        : "r"(a[0]), "r"(a[1]), "r"(a[2]), "r"(a[3]), "r"(b[0]), "r"(b[1]));
}
__device__ __forceinline__ void mma_f16(float* d, const uint32_t* a, const uint32_t* b){
    asm volatile(
        "mma.sync.aligned.m16n8k16.row.col.f32.f16.f16.f32 "
        "{%0,%1,%2,%3}, {%4,%5,%6,%7}, {%8,%9}, {%0,%1,%2,%3};"
        : "+f"(d[0]), "+f"(d[1]), "+f"(d[2]), "+f"(d[3])
        : "r"(a[0]), "r"(a[1]), "r"(a[2]), "r"(a[3]), "r"(b[0]), "r"(b[1]));
}
__device__ __forceinline__ void cp16(uint32_t saddr, const void* g){
    asm volatile("cp.async.cg.shared.global [%0], [%1], 16;" :: "r"(saddr), "l"(g));
}
__device__ __forceinline__ uint32_t packh2(__half a, __half b){
    uint32_t lo = (uint32_t)__half_as_ushort(a);
    uint32_t hi = (uint32_t)__half_as_ushort(b);
    return (hi << 16) | lo;
}
__device__ __forceinline__ void h16split(float v, __half& h, __half& l){
    h = __float2half_rn(v);
    l = __float2half_rn(v - __half2float(h));
}
__device__ __forceinline__ uint32_t smem_u32(const void* p){
    return (uint32_t)__cvta_generic_to_shared(p);
}

// ---------------- device globals ----------------
__device__ uint32_t g_wfh[9*4*8*64];     // conv weights fp16x2 hi [tap][cg][ci-pair][co]
__device__ uint32_t g_wfl[9*4*8*64];     // fp16x2 lo residual
__device__ float g_bnscale[64];
__device__ float g_bnshift[64];
__device__ float g_w32[DIM*FEAT];        // proj_w tf32 bits
__device__ float g_a32[(long)M_TOK*FEAT];// masked patches tf32 bits

// =====================================================================
// Kernel 0: conv-weight fp16-split repack + BN fold + proj_w tf32 convert
// =====================================================================
__global__ void prep_kernel(const float* __restrict__ cw,
                            const float* __restrict__ cb,
                            const float* __restrict__ gamma,
                            const float* __restrict__ beta,
                            const float* __restrict__ mean,
                            const float* __restrict__ var,
                            const float* __restrict__ pw)
{
    int idx = blockIdx.x*256 + threadIdx.x;
    if (idx < 9*4*8*64){
        int co  = idx & 63;
        int c   = (idx >> 6) & 7;
        int cg  = (idx >> 9) & 3;
        int tap = idx >> 11;
        int ci0 = cg*16 + 2*c;
        float w0 = cw[(co*64 + ci0)*9 + tap];
        float w1 = cw[(co*64 + ci0 + 1)*9 + tap];
        __half h0, l0, h1, l1;
        h16split(w0, h0, l0);
        h16split(w1, h1, l1);
        g_wfh[idx] = packh2(h0, h1);
        g_wfl[idx] = packh2(l0, l1);
    }
    if (idx < DIM*FEAT)
        g_w32[idx] = __uint_as_float(f2tf32(pw[idx]));
    if (blockIdx.x == 0 && threadIdx.x < 64){
        int co = threadIdx.x;
        float s = gamma[co] * rsqrtf(var[co] + 1e-5f);
        g_bnscale[co] = s;
        g_bnshift[co] = (cb[co] - mean[co]) * s + beta[co];
    }
}

// =====================================================================
// Kernel 1: conv3x3 implicit GEMM, 2-term fp16 legacy mma:
//   acc += xh * wh ; acc += xh * wl     (x single fp16, w exact 2xfp16)
// Round-10 structure: whole-cg B prestaging (cp.async), 2 barriers/cg,
// round-6 conflict-free fragment layouts. Halo smem HALVED (single s_x).
// =====================================================================
#define CV_SX 1600                 // 8 ci-pairs x 10 y x 20 x (stride 200)
#define CV_SB (9*8*72)             // 9 taps x 8 ci-pairs x co (pad 72)
#define CV_SMEM_BYTES ((CV_SX + 2*CV_SB)*4)   // 47,872

__global__ __launch_bounds__(256, 2) void conv_mma_kernel(
    const float* __restrict__ x,
    const float* __restrict__ mask,
    float* __restrict__ out_patches)
{
    extern __shared__ __align__(16) uint32_t dynsm[];
    uint32_t* s_x  = dynsm;                    // [c][y][x] : c*200+y*20+x
    uint32_t* s_bh = dynsm + CV_SX;            // [tap][c][co] : (tap*8+c)*72+co
    uint32_t* s_bl = dynsm + CV_SX + CV_SB;

    __shared__ float s_mask[36];
    __shared__ float s_scale[64], s_shift[64];

    const int tid  = threadIdx.x;
    const int lane = tid & 31;
    const int wid  = tid >> 5;
    const int wm   = wid & 3;
    const int wn   = wid >> 2;
    const int lg   = lane >> 2;      // 0..7
    const int lt   = lane & 3;       // 0..3

    const int w0    = blockIdx.x * 16;
    const int h0    = blockIdx.y * 8;
    const int frame = blockIdx.z;
    const float* xf = x + (long)frame * FRAME_STRIDE;

    if (tid < 36) s_mask[tid] = mask[tid];
    if (tid < 64){ s_scale[tid] = g_bnscale[tid]; s_shift[tid] = g_bnshift[tid]; }

    float acc[2][4][4];
    #pragma unroll
    for (int mt=0;mt<2;mt++)
        #pragma unroll
        for (int nt=0;nt<4;nt++)
            #pragma unroll
            for (int r=0;r<4;r++) acc[mt][nt][r] = 0.f;

    for (int cg = 0; cg < 4; cg++){
        __syncthreads();   // previous cg's reads of s_x/s_b* complete

        // ---- cp.async: all 9 taps of B (wh & wl) for this cg ----
        for (int i = tid; i < 1152; i += 256){
            int q = i & 15;
            int c = (i >> 4) & 7;
            int j = i >> 7;
            uint32_t soff = (uint32_t)(((j*8 + c)*72 + q*4) * 4);
            long goff = ((long)(j*4 + cg)*8 + c)*64 + q*4;
            cp16(smem_u32(s_bh) + soff, g_wfh + goff);
            cp16(smem_u32(s_bl) + soff, g_wfl + goff);
        }
        asm volatile("cp.async.commit_group;" ::: "memory");

        // ---- halo stage (LDG + fp16 cvt + STS), overlaps cp.async ----
        for (int i = tid; i < 1600; i += 256){
            int c  = i / 200;
            int r2 = i - c*200;
            int yy = r2 / 20;
            int xx = r2 - yy*20;
            int gy = h0 + yy - 1, gx = w0 + xx - 1;
            float v0 = 0.f, v1 = 0.f;
            if (gy >= 0 && gy < H && gx >= 0 && gx < W){
                long base = (long)(cg*16 + 2*c)*(H*W) + gy*W + gx;
                v0 = xf[base];
                v1 = xf[base + H*W];
            }
            s_x[i] = packh2(__float2half_rn(v0), __float2half_rn(v1));
        }
        asm volatile("cp.async.wait_group 0;" ::: "memory");
        __syncthreads();

        // ---- 9 taps, no barriers ----
        #pragma unroll
        for (int tap = 0; tap < 9; tap++){
            const int ky = tap / 3, kx = tap - ky*3;
            uint32_t a[2][4], bh[4][2], bl[4][2];
            #pragma unroll
            for (int mt = 0; mt < 2; mt++){
                const int py = wm*2 + mt + ky;
                const int px = lg + kx;
                const int b0 = lt*200     + py*20 + px;
                const int b1 = (lt+4)*200 + py*20 + px;
                a[mt][0] = s_x[b0];
                a[mt][1] = s_x[b0 + 8];
                a[mt][2] = s_x[b1];
                a[mt][3] = s_x[b1 + 8];
            }
            #pragma unroll
            for (int nt = 0; nt < 4; nt++){
                const int co = wn*32 + nt*8 + lg;
                bh[nt][0] = s_bh[(tap*8 + lt  )*72 + co];
                bh[nt][1] = s_bh[(tap*8 + lt+4)*72 + co];
                bl[nt][0] = s_bl[(tap*8 + lt  )*72 + co];
                bl[nt][1] = s_bl[(tap*8 + lt+4)*72 + co];
            }
            #pragma unroll
            for (int mt = 0; mt < 2; mt++)
                #pragma unroll
                for (int nt = 0; nt < 4; nt++){
                    mma_f16(acc[mt][nt], a[mt], bh[nt]);   // x * w_hi
                    mma_f16(acc[mt][nt], a[mt], bl[nt]);   // x * w_lo
                }
        }
    }

    // ---- epilogue: BN + GELU + mask -> patches + tf32 copy ----
    #pragma unroll
    for (int mt = 0; mt < 2; mt++){
        const int r0 = wm*32 + mt*16 + lg;
        #pragma unroll
        for (int dr = 0; dr < 2; dr++){
            const int r = r0 + dr*8;
            const int hh = h0 + (r >> 4);
            const int ww = w0 + (r & 15);
            const int l = hh / 6, i_in = hh - l*6;
            const int rr = ww / 6, j_in = ww - rr*6;
            const float mk = s_mask[i_in*6 + j_in];
            const long arow = ((long)frame*256 + l*16 + rr)*FEAT;
            #pragma unroll
            for (int nt = 0; nt < 4; nt++){
                const int c0 = wn*32 + nt*8 + (lt << 1);
                #pragma unroll
                for (int dc = 0; dc < 2; dc++){
                    const int co = c0 + dc;
                    const float v = acc[mt][nt][dr*2 + dc];
                    float o = gelu_exact(v*s_scale[co] + s_shift[co]) * mk;
                    const long k = arow + co*36 + i_in*6 + j_in;
                    out_patches[k] = o;
                    g_a32[k] = __uint_as_float(f2tf32(o));
                }
            }
        }
    }
}

// =====================================================================
// Kernel 2: tokens = gelu(A @ Wp^T + bias), tf32 mma + cp.async pipeline
// (round-5/6/10 kernel, known good, unchanged)
// =====================================================================
#define GBM 128
#define GBN 64
#define GBK 32
#define KSTR 36
#define STAGES 3
#define SA_WORDS (GBM*KSTR)
#define SB_WORDS (GBN*KSTR)
#define GEMM_SMEM_BYTES ((STAGES*(SA_WORDS+SB_WORDS))*4)   // 82944

__global__ __launch_bounds__(256, 2) void gemm_tokens_cp_kernel(
    const float* __restrict__ bias,
    float* __restrict__ tok)
{
    extern __shared__ uint32_t smdyn[];
    uint32_t* s_a = smdyn;
    uint32_t* s_b = smdyn + STAGES*SA_WORDS;
    const uint32_t sa_base = smem_u32(s_a);
    const uint32_t sb_base = smem_u32(s_b);

    const int tid  = threadIdx.x;
    const int lane = tid & 31;
    const int wid  = tid >> 5;
    const int wm   = wid & 3;
    const int wn   = wid >> 2;
    const int bm   = blockIdx.y;
    const int bn   = blockIdx.x;

    const float* Ab = g_a32 + (long)bm*GBM*FEAT;
    const float* Bb = g_w32 + (long)bn*GBN*FEAT;

    float acc[2][4][4];
    #pragma unroll
    for (int mt=0;mt<2;mt++)
        #pragma unroll
        for (int nt=0;nt<4;nt++)
            #pragma unroll
            for (int r=0;r<4;r++) acc[mt][nt][r] = 0.f;

    const int crowA = tid >> 3;
    const int ck4   = (tid & 7) << 2;

    #pragma unroll
    for (int st = 0; st < 2; st++){
        const int kg = st*GBK;
        #pragma unroll
        for (int j = 0; j < 4; j++){
            int row = crowA + j*32;
            cp16(sa_base + (uint32_t)((st*GBM + row)*KSTR + ck4)*4,
                 Ab + (long)row*FEAT + kg + ck4);
        }
        #pragma unroll
        for (int j = 0; j < 2; j++){
            int row = crowA + j*32;
            if (row < GBN)
                cp16(sb_base + (uint32_t)((st*GBN + row)*KSTR + ck4)*4,
                     Bb + (long)row*FEAT + kg + ck4);
        }
        asm volatile("cp.async.commit_group;");
    }
    asm volatile("cp.async.wait_group 1;");
    __syncthreads();

    const int NKT = FEAT / GBK;   // 72
    for (int kt = 0; kt < NKT; kt++){
        const int cur = kt % STAGES;
        if (kt + 2 < NKT){
            const int st = (kt + 2) % STAGES;
            const int kg = (kt + 2)*GBK;
            #pragma unroll
            for (int j = 0; j < 4; j++){
                int row = crowA + j*32;
                cp16(sa_base + (uint32_t)((st*GBM + row)*KSTR + ck4)*4,
                     Ab + (long)row*FEAT + kg + ck4);
            }
            #pragma unroll
            for (int j = 0; j < 2; j++){
                int row = crowA + j*32;
                if (row < GBN)
                    cp16(sb_base + (uint32_t)((st*GBN + row)*KSTR + ck4)*4,
                         Bb + (long)row*FEAT + kg + ck4);
            }
        }
        asm volatile("cp.async.commit_group;");

        const uint32_t* pa = s_a + cur*SA_WORDS;
        const uint32_t* pb = s_b + cur*SB_WORDS;
        #pragma unroll
        for (int ks = 0; ks < 4; ks++){
            const int kb = ks*8 + (lane & 3);
            uint32_t af[2][4], bf[4][2];
            #pragma unroll
            for (int mt=0;mt<2;mt++){
                int r0 = wm*32 + mt*16 + (lane >> 2);
                af[mt][0] = pa[r0*KSTR + kb];
                af[mt][1] = pa[(r0+8)*KSTR + kb];
                af[mt][2] = pa[r0*KSTR + kb + 4];
                af[mt][3] = pa[(r0+8)*KSTR + kb + 4];
            }
            #pragma unroll
            for (int nt=0;nt<4;nt++){
                int c0 = wn*32 + nt*8 + (lane >> 2);
                bf[nt][0] = pb[c0*KSTR + kb];
                bf[nt][1] = pb[c0*KSTR + kb + 4];
            }
            #pragma unroll
            for (int mt=0;mt<2;mt++)
                #pragma unroll
                for (int nt=0;nt<4;nt++)
                    mma_tf32(acc[mt][nt], af[mt], bf[nt]);
        }

        asm volatile("cp.async.wait_group 1;");
        __syncthreads();
    }

    #pragma unroll
    for (int mt=0;mt<2;mt++){
        const int r0 = bm*GBM + wm*32 + mt*16 + (lane >> 2);
        #pragma unroll
        for (int nt=0;nt<4;nt++){
            const int c0 = bn*GBN + wn*32 + nt*8 + ((lane & 3) << 1);
            float2 b2 = *(const float2*)(bias + c0);
            float2 o0, o1;
            o0.x = gelu_exact(acc[mt][nt][0] + b2.x);
            o0.y = gelu_exact(acc[mt][nt][1] + b2.y);
            o1.x = gelu_exact(acc[mt][nt][2] + b2.x);
            o1.y = gelu_exact(acc[mt][nt][3] + b2.y);
            *(float2*)(tok + (long)r0*DIM + c0)     = o0;
            *(float2*)(tok + (long)(r0+8)*DIM + c0) = o1;
        }
    }
}

// =====================================================================
extern "C" void kernel_launch(void* const* d_in, const int* in_sizes, int n_in,
                              void* d_out, int out_size)
{
    const float* x      = (const float*)d_in[0];
    const float* conv_w = (const float*)d_in[1];
    const float* conv_b = (const float*)d_in[2];
    const float* gamma  = (const float*)d_in[3];
    const float* beta   = (const float*)d_in[4];
    const float* mean   = (const float*)d_in[5];
    const float* var    = (const float*)d_in[6];
    const float* proj_w = (const float*)d_in[7];
    const float* proj_b = (const float*)d_in[8];
    const float* mask   = (const float*)d_in[9];

    float* tokens  = (float*)d_out;                 // [8192, 768]
    float* patches = (float*)d_out + TOK_ELEMS;     // [8192, 2304]

    cudaFuncSetAttribute(conv_mma_kernel,
                         cudaFuncAttributeMaxDynamicSharedMemorySize,
                         CV_SMEM_BYTES);
    cudaFuncSetAttribute(gemm_tokens_cp_kernel,
                         cudaFuncAttributeMaxDynamicSharedMemorySize,
                         GEMM_SMEM_BYTES);

    // 0) weight repack (fp16 split) + BN fold + proj_w tf32 convert
    prep_kernel<<<(DIM*FEAT + 255)/256, 256>>>(conv_w, conv_b, gamma, beta,
                                               mean, var, proj_w);

    // 1) conv as implicit GEMM (2-term fp16) -> patches + tf32 A copy
    {
        dim3 grid(W/16, H/8, NF);
        conv_mma_kernel<<<grid, 256, CV_SMEM_BYTES>>>(x, mask, patches);
    }

    // 2) projection GEMM + bias + GELU (cp.async pipelined tf32 mma)
    {
        dim3 grid(DIM/GBN, M_TOK/GBM);
        gemm_tokens_cp_kernel<<<grid, 256, GEMM_SMEM_BYTES>>>(proj_b, tokens);
    }
}

// round 12
// speedup vs baseline: 1.6680x; 1.2725x over previous
#include <cuda_runtime.h>
#include <cuda_fp16.h>
#include <math.h>
#include <stdint.h>

// ---------------- problem constants ----------------
#define NF      32
#define C       64
#define H       96
#define W       96
#define FEAT    2304
#define DIM     768
#define M_TOK   (NF*256)                    // 8192
#define TOK_ELEMS   (M_TOK*DIM)
#define FRAME_STRIDE (C*H*W)

__device__ __forceinline__ float gelu_exact(float x){
    return 0.5f*x*(1.0f + erff(x*0.7071067811865476f));
}
__device__ __forceinline__ void mma_f16(float* d, const uint32_t* a, const uint32_t* b){
    asm volatile(
        "mma.sync.aligned.m16n8k16.row.col.f32.f16.f16.f32 "
        "{%0,%1,%2,%3}, {%4,%5,%6,%7}, {%8,%9}, {%0,%1,%2,%3};"
        : "+f"(d[0]), "+f"(d[1]), "+f"(d[2]), "+f"(d[3])
        : "r"(a[0]), "r"(a[1]), "r"(a[2]), "r"(a[3]), "r"(b[0]), "r"(b[1]));
}
__device__ __forceinline__ void cp16(uint32_t saddr, const void* g){
    asm volatile("cp.async.cg.shared.global [%0], [%1], 16;" :: "r"(saddr), "l"(g));
}
__device__ __forceinline__ uint32_t packh2(__half a, __half b){
    uint32_t lo = (uint32_t)__half_as_ushort(a);
    uint32_t hi = (uint32_t)__half_as_ushort(b);
    return (hi << 16) | lo;
}
__device__ __forceinline__ void h16split(float v, __half& h, __half& l){
    h = __float2half_rn(v);
    l = __float2half_rn(v - __half2float(h));
}
__device__ __forceinline__ uint32_t smem_u32(const void* p){
    return (uint32_t)__cvta_generic_to_shared(p);
}

// ---------------- device globals ----------------
__device__ uint32_t g_wfh[9*4*8*64];     // conv weights fp16x2 hi [tap][cg][ci-pair][co]
__device__ uint32_t g_wfl[9*4*8*64];     // fp16x2 lo residual
__device__ float g_bnscale[64];
__device__ float g_bnshift[64];
__device__ __half g_w16[DIM*FEAT];       // proj_w fp16
__device__ __half g_a16[(long)M_TOK*FEAT]; // masked patches fp16

// =====================================================================
// Kernel 0: conv-weight fp16-split repack + BN fold + proj_w fp16 convert
// =====================================================================
__global__ void prep_kernel(const float* __restrict__ cw,
                            const float* __restrict__ cb,
                            const float* __restrict__ gamma,
                            const float* __restrict__ beta,
                            const float* __restrict__ mean,
                            const float* __restrict__ var,
                            const float* __restrict__ pw)
{
    int idx = blockIdx.x*256 + threadIdx.x;
    if (idx < 9*4*8*64){
        int co  = idx & 63;
        int c   = (idx >> 6) & 7;
        int cg  = (idx >> 9) & 3;
        int tap = idx >> 11;
        int ci0 = cg*16 + 2*c;
        float w0 = cw[(co*64 + ci0)*9 + tap];
        float w1 = cw[(co*64 + ci0 + 1)*9 + tap];
        __half h0, l0, h1, l1;
        h16split(w0, h0, l0);
        h16split(w1, h1, l1);
        g_wfh[idx] = packh2(h0, h1);
        g_wfl[idx] = packh2(l0, l1);
    }
    if (idx < DIM*FEAT)
        g_w16[idx] = __float2half_rn(pw[idx]);
    if (blockIdx.x == 0 && threadIdx.x < 64){
        int co = threadIdx.x;
        float s = gamma[co] * rsqrtf(var[co] + 1e-5f);
        g_bnscale[co] = s;
        g_bnshift[co] = (cb[co] - mean[co]) * s + beta[co];
    }
}

// =====================================================================
// Kernel 1: conv3x3 implicit GEMM, 2-term fp16 legacy mma
// (round-11 kernel; epilogue now writes fp16 A copy)
// =====================================================================
#define CV_SX 1600                 // 8 ci-pairs x 10 y x 20 x (stride 200)
#define CV_SB (9*8*72)             // 9 taps x 8 ci-pairs x co (pad 72)
#define CV_SMEM_BYTES ((CV_SX + 2*CV_SB)*4)   // 47,872

__global__ __launch_bounds__(256, 2) void conv_mma_kernel(
    const float* __restrict__ x,
    const float* __restrict__ mask,
    float* __restrict__ out_patches)
{
    extern __shared__ __align__(16) uint32_t dynsm[];
    uint32_t* s_x  = dynsm;                    // [c][y][x] : c*200+y*20+x
    uint32_t* s_bh = dynsm + CV_SX;            // [tap][c][co] : (tap*8+c)*72+co
    uint32_t* s_bl = dynsm + CV_SX + CV_SB;

    __shared__ float s_mask[36];
    __shared__ float s_scale[64], s_shift[64];

    const int tid  = threadIdx.x;
    const int lane = tid & 31;
    const int wid  = tid >> 5;
    const int wm   = wid & 3;
    const int wn   = wid >> 2;
    const int lg   = lane >> 2;      // 0..7
    const int lt   = lane & 3;       // 0..3

    const int w0    = blockIdx.x * 16;
    const int h0    = blockIdx.y * 8;
    const int frame = blockIdx.z;
    const float* xf = x + (long)frame * FRAME_STRIDE;

    if (tid < 36) s_mask[tid] = mask[tid];
    if (tid < 64){ s_scale[tid] = g_bnscale[tid]; s_shift[tid] = g_bnshift[tid]; }

    float acc[2][4][4];
    #pragma unroll
    for (int mt=0;mt<2;mt++)
        #pragma unroll
        for (int nt=0;nt<4;nt++)
            #pragma unroll
            for (int r=0;r<4;r++) acc[mt][nt][r] = 0.f;

    for (int cg = 0; cg < 4; cg++){
        __syncthreads();   // previous cg's reads of s_x/s_b* complete

        // ---- cp.async: all 9 taps of B (wh & wl) for this cg ----
        for (int i = tid; i < 1152; i += 256){
            int q = i & 15;
            int c = (i >> 4) & 7;
            int j = i >> 7;
            uint32_t soff = (uint32_t)(((j*8 + c)*72 + q*4) * 4);
            long goff = ((long)(j*4 + cg)*8 + c)*64 + q*4;
            cp16(smem_u32(s_bh) + soff, g_wfh + goff);
            cp16(smem_u32(s_bl) + soff, g_wfl + goff);
        }
        asm volatile("cp.async.commit_group;" ::: "memory");

        // ---- halo stage (LDG + fp16 cvt + STS), overlaps cp.async ----
        for (int i = tid; i < 1600; i += 256){
            int c  = i / 200;
            int r2 = i - c*200;
            int yy = r2 / 20;
            int xx = r2 - yy*20;
            int gy = h0 + yy - 1, gx = w0 + xx - 1;
            float v0 = 0.f, v1 = 0.f;
            if (gy >= 0 && gy < H && gx >= 0 && gx < W){
                long base = (long)(cg*16 + 2*c)*(H*W) + gy*W + gx;
                v0 = xf[base];
                v1 = xf[base + H*W];
            }
            s_x[i] = packh2(__float2half_rn(v0), __float2half_rn(v1));
        }
        asm volatile("cp.async.wait_group 0;" ::: "memory");
        __syncthreads();

        // ---- 9 taps, no barriers ----
        #pragma unroll
        for (int tap = 0; tap < 9; tap++){
            const int ky = tap / 3, kx = tap - ky*3;
            uint32_t a[2][4], bh[4][2], bl[4][2];
            #pragma unroll
            for (int mt = 0; mt < 2; mt++){
                const int py = wm*2 + mt + ky;
                const int px = lg + kx;
                const int b0 = lt*200     + py*20 + px;
                const int b1 = (lt+4)*200 + py*20 + px;
                a[mt][0] = s_x[b0];
                a[mt][1] = s_x[b0 + 8];
                a[mt][2] = s_x[b1];
                a[mt][3] = s_x[b1 + 8];
            }
            #pragma unroll
            for (int nt = 0; nt < 4; nt++){
                const int co = wn*32 + nt*8 + lg;
                bh[nt][0] = s_bh[(tap*8 + lt  )*72 + co];
                bh[nt][1] = s_bh[(tap*8 + lt+4)*72 + co];
                bl[nt][0] = s_bl[(tap*8 + lt  )*72 + co];
                bl[nt][1] = s_bl[(tap*8 + lt+4)*72 + co];
            }
            #pragma unroll
            for (int mt = 0; mt < 2; mt++)
                #pragma unroll
                for (int nt = 0; nt < 4; nt++){
                    mma_f16(acc[mt][nt], a[mt], bh[nt]);   // x * w_hi
                    mma_f16(acc[mt][nt], a[mt], bl[nt]);   // x * w_lo
                }
        }
    }

    // ---- epilogue: BN + GELU + mask -> patches (fp32) + fp16 A copy ----
    #pragma unroll
    for (int mt = 0; mt < 2; mt++){
        const int r0 = wm*32 + mt*16 + lg;
        #pragma unroll
        for (int dr = 0; dr < 2; dr++){
            const int r = r0 + dr*8;
            const int hh = h0 + (r >> 4);
            const int ww = w0 + (r & 15);
            const int l = hh / 6, i_in = hh - l*6;
            const int rr = ww / 6, j_in = ww - rr*6;
            const float mk = s_mask[i_in*6 + j_in];
            const long arow = ((long)frame*256 + l*16 + rr)*FEAT;
            #pragma unroll
            for (int nt = 0; nt < 4; nt++){
                const int c0 = wn*32 + nt*8 + (lt << 1);
                #pragma unroll
                for (int dc = 0; dc < 2; dc++){
                    const int co = c0 + dc;
                    const float v = acc[mt][nt][dr*2 + dc];
                    float o = gelu_exact(v*s_scale[co] + s_shift[co]) * mk;
                    const long k = arow + co*36 + i_in*6 + j_in;
                    out_patches[k] = o;
                    g_a16[k] = __float2half_rn(o);
                }
            }
        }
    }
}

// =====================================================================
// Kernel 2: tokens = gelu(A @ Wp^T + bias), fp16 m16n8k16 + cp.async
// pipeline. Same structure/indexing as the proven tf32 kernel, but
// GBK = 64 fp16 (32 u32/row), NKT halved to 36, mma count halved.
// =====================================================================
#define GBM 128
#define GBN 64
#define GBK 64                      // fp16 elements per tile
#define KSTR 36                     // u32 words per row (32 data + 4 pad)
#define STAGES 3
#define SA_WORDS (GBM*KSTR)
#define SB_WORDS (GBN*KSTR)
#define GEMM_SMEM_BYTES ((STAGES*(SA_WORDS+SB_WORDS))*4)   // 82944

__global__ __launch_bounds__(256, 2) void gemm_tokens_f16_kernel(
    const float* __restrict__ bias,
    float* __restrict__ tok)
{
    extern __shared__ uint32_t smdyn[];
    uint32_t* s_a = smdyn;
    uint32_t* s_b = smdyn + STAGES*SA_WORDS;
    const uint32_t sa_base = smem_u32(s_a);
    const uint32_t sb_base = smem_u32(s_b);

    const int tid  = threadIdx.x;
    const int lane = tid & 31;
    const int wid  = tid >> 5;
    const int wm   = wid & 3;
    const int wn   = wid >> 2;
    const int bm   = blockIdx.y;
    const int bn   = blockIdx.x;

    const __half* Ab = g_a16 + (long)bm*GBM*FEAT;
    const __half* Bb = g_w16 + (long)bn*GBN*FEAT;

    float acc[2][4][4];
    #pragma unroll
    for (int mt=0;mt<2;mt++)
        #pragma unroll
        for (int nt=0;nt<4;nt++)
            #pragma unroll
            for (int r=0;r<4;r++) acc[mt][nt][r] = 0.f;

    const int crowA = tid >> 3;          // row base (j adds 32)
    const int ck4   = (tid & 7) << 2;    // u32 chunk offset within row
    const int ckh   = ck4 << 1;          // fp16 element offset

    #pragma unroll
    for (int st = 0; st < 2; st++){
        const int kg = st*GBK;
        #pragma unroll
        for (int j = 0; j < 4; j++){
            int row = crowA + j*32;
            cp16(sa_base + (uint32_t)((st*GBM + row)*KSTR + ck4)*4,
                 Ab + (long)row*FEAT + kg + ckh);
        }
        #pragma unroll
        for (int j = 0; j < 2; j++){
            int row = crowA + j*32;
            if (row < GBN)
                cp16(sb_base + (uint32_t)((st*GBN + row)*KSTR + ck4)*4,
                     Bb + (long)row*FEAT + kg + ckh);
        }
        asm volatile("cp.async.commit_group;");
    }
    asm volatile("cp.async.wait_group 1;");
    __syncthreads();

    const int NKT = FEAT / GBK;   // 36
    for (int kt = 0; kt < NKT; kt++){
        const int cur = kt % STAGES;
        if (kt + 2 < NKT){
            const int st = (kt + 2) % STAGES;
            const int kg = (kt + 2)*GBK;
            #pragma unroll
            for (int j = 0; j < 4; j++){
                int row = crowA + j*32;
                cp16(sa_base + (uint32_t)((st*GBM + row)*KSTR + ck4)*4,
                     Ab + (long)row*FEAT + kg + ckh);
            }
            #pragma unroll
            for (int j = 0; j < 2; j++){
                int row = crowA + j*32;
                if (row < GBN)
                    cp16(sb_base + (uint32_t)((st*GBN + row)*KSTR + ck4)*4,
                         Bb + (long)row*FEAT + kg + ckh);
            }
        }
        asm volatile("cp.async.commit_group;");

        const uint32_t* pa = s_a + cur*SA_WORDS;
        const uint32_t* pb = s_b + cur*SB_WORDS;
        #pragma unroll
        for (int ks = 0; ks < 4; ks++){
            const int kb = ks*8 + (lane & 3);   // k-pair index (16 fp16 per step)
            uint32_t af[2][4], bf[4][2];
            #pragma unroll
            for (int mt=0;mt<2;mt++){
                int r0 = wm*32 + mt*16 + (lane >> 2);
                af[mt][0] = pa[r0*KSTR + kb];
                af[mt][1] = pa[(r0+8)*KSTR + kb];
                af[mt][2] = pa[r0*KSTR + kb + 4];
                af[mt][3] = pa[(r0+8)*KSTR + kb + 4];
            }
            #pragma unroll
            for (int nt=0;nt<4;nt++){
                int c0 = wn*32 + nt*8 + (lane >> 2);
                bf[nt][0] = pb[c0*KSTR + kb];
                bf[nt][1] = pb[c0*KSTR + kb + 4];
            }
            #pragma unroll
            for (int mt=0;mt<2;mt++)
                #pragma unroll
                for (int nt=0;nt<4;nt++)
                    mma_f16(acc[mt][nt], af[mt], bf[nt]);
        }

        asm volatile("cp.async.wait_group 1;");
        __syncthreads();
    }

    #pragma unroll
    for (int mt=0;mt<2;mt++){
        const int r0 = bm*GBM + wm*32 + mt*16 + (lane >> 2);
        #pragma unroll
        for (int nt=0;nt<4;nt++){
            const int c0 = bn*GBN + wn*32 + nt*8 + ((lane & 3) << 1);
            float2 b2 = *(const float2*)(bias + c0);
            float2 o0, o1;
            o0.x = gelu_exact(acc[mt][nt][0] + b2.x);
            o0.y = gelu_exact(acc[mt][nt][1] + b2.y);
            o1.x = gelu_exact(acc[mt][nt][2] + b2.x);
            o1.y = gelu_exact(acc[mt][nt][3] + b2.y);
            *(float2*)(tok + (long)r0*DIM + c0)     = o0;
            *(float2*)(tok + (long)(r0+8)*DIM + c0) = o1;
        }
    }
}

// =====================================================================
extern "C" void kernel_launch(void* const* d_in, const int* in_sizes, int n_in,
                              void* d_out, int out_size)
{
    const float* x      = (const float*)d_in[0];
    const float* conv_w = (const float*)d_in[1];
    const float* conv_b = (const float*)d_in[2];
    const float* gamma  = (const float*)d_in[3];
    const float* beta   = (const float*)d_in[4];
    const float* mean   = (const float*)d_in[5];
    const float* var    = (const float*)d_in[6];
    const float* proj_w = (const float*)d_in[7];
    const float* proj_b = (const float*)d_in[8];
    const float* mask   = (const float*)d_in[9];

    float* tokens  = (float*)d_out;                 // [8192, 768]
    float* patches = (float*)d_out + TOK_ELEMS;     // [8192, 2304]

    cudaFuncSetAttribute(conv_mma_kernel,
                         cudaFuncAttributeMaxDynamicSharedMemorySize,
                         CV_SMEM_BYTES);
    cudaFuncSetAttribute(gemm_tokens_f16_kernel,
                         cudaFuncAttributeMaxDynamicSharedMemorySize,
                         GEMM_SMEM_BYTES);

    // 0) weight repack (fp16 split) + BN fold + proj_w fp16 convert
    prep_kernel<<<(DIM*FEAT + 255)/256, 256>>>(conv_w, conv_b, gamma, beta,
                                               mean, var, proj_w);

    // 1) conv as implicit GEMM (2-term fp16) -> patches + fp16 A copy
    {
        dim3 grid(W/16, H/8, NF);
        conv_mma_kernel<<<grid, 256, CV_SMEM_BYTES>>>(x, mask, patches);
    }

    // 2) projection GEMM + bias + GELU (fp16 m16n8k16, cp.async pipeline)
    {
        dim3 grid(DIM/GBN, M_TOK/GBM);
        gemm_tokens_f16_kernel<<<grid, 256, GEMM_SMEM_BYTES>>>(proj_b, tokens);
    }
}

// round 13
// speedup vs baseline: 1.8416x; 1.1041x over previous
#include <cuda_runtime.h>
#include <cuda_fp16.h>
#include <math.h>
#include <stdint.h>

// ---------------- problem constants ----------------
#define NF      32
#define C       64
#define H       96
#define W       96
#define FEAT    2304
#define DIM     768
#define M_TOK   (NF*256)                    // 8192
#define TOK_ELEMS   (M_TOK*DIM)
#define FRAME_STRIDE (C*H*W)

__device__ __forceinline__ float gelu_exact(float x){
    return 0.5f*x*(1.0f + erff(x*0.7071067811865476f));
}
__device__ __forceinline__ void mma_f16(float* d, const uint32_t* a, const uint32_t* b){
    asm volatile(
        "mma.sync.aligned.m16n8k16.row.col.f32.f16.f16.f32 "
        "{%0,%1,%2,%3}, {%4,%5,%6,%7}, {%8,%9}, {%0,%1,%2,%3};"
        : "+f"(d[0]), "+f"(d[1]), "+f"(d[2]), "+f"(d[3])
        : "r"(a[0]), "r"(a[1]), "r"(a[2]), "r"(a[3]), "r"(b[0]), "r"(b[1]));
}
__device__ __forceinline__ void cp16(uint32_t saddr, const void* g){
    asm volatile("cp.async.cg.shared.global [%0], [%1], 16;" :: "r"(saddr), "l"(g));
}
__device__ __forceinline__ uint32_t packh2(__half a, __half b){
    uint32_t lo = (uint32_t)__half_as_ushort(a);
    uint32_t hi = (uint32_t)__half_as_ushort(b);
    return (hi << 16) | lo;
}
__device__ __forceinline__ uint32_t smem_u32(const void* p){
    return (uint32_t)__cvta_generic_to_shared(p);
}

// ---------------- device globals ----------------
__device__ uint32_t g_wf[9*4*8*64];      // conv weights fp16x2 [tap][cg][ci-pair][co]
__device__ float g_bnscale[64];
__device__ float g_bnshift[64];
__device__ __half g_w16[DIM*FEAT];       // proj_w fp16
__device__ __half g_a16[(long)M_TOK*FEAT]; // masked patches fp16

// =====================================================================
// Kernel 0: conv-weight fp16 repack + BN fold + proj_w fp16 convert
// =====================================================================
__global__ void prep_kernel(const float* __restrict__ cw,
                            const float* __restrict__ cb,
                            const float* __restrict__ gamma,
                            const float* __restrict__ beta,
                            const float* __restrict__ mean,
                            const float* __restrict__ var,
                            const float* __restrict__ pw)
{
    int idx = blockIdx.x*256 + threadIdx.x;
    if (idx < 9*4*8*64){
        int co  = idx & 63;
        int c   = (idx >> 6) & 7;
        int cg  = (idx >> 9) & 3;
        int tap = idx >> 11;
        int ci0 = cg*16 + 2*c;
        float w0 = cw[(co*64 + ci0)*9 + tap];
        float w1 = cw[(co*64 + ci0 + 1)*9 + tap];
        g_wf[idx] = packh2(__float2half_rn(w0), __float2half_rn(w1));
    }
    if (idx < DIM*FEAT)
        g_w16[idx] = __float2half_rn(pw[idx]);
    if (blockIdx.x == 0 && threadIdx.x < 64){
        int co = threadIdx.x;
        float s = gamma[co] * rsqrtf(var[co] + 1e-5f);
        g_bnscale[co] = s;
        g_bnshift[co] = (cb[co] - mean[co]) * s + beta[co];
    }
}

// =====================================================================
// Kernel 1: conv3x3 implicit GEMM, single-term fp16 legacy mma
// (x fp16, w fp16, fp32 accumulate). Whole-cg B prestaging (cp.async),
// 2 barriers/cg, conflict-free fragment layouts. smem 16.8 KB.
// =====================================================================
#define CV_SX 1600                 // 8 ci-pairs x 10 y x 20 x (stride 200)
#define CV_SB (9*8*72)             // 9 taps x 8 ci-pairs x co (pad 72)
#define CV_SMEM_BYTES ((CV_SX + CV_SB)*4)   // 16,768

__global__ __launch_bounds__(256, 2) void conv_mma_kernel(
    const float* __restrict__ x,
    const float* __restrict__ mask,
    float* __restrict__ out_patches)
{
    extern __shared__ __align__(16) uint32_t dynsm[];
    uint32_t* s_x = dynsm;                    // [c][y][x] : c*200+y*20+x
    uint32_t* s_b = dynsm + CV_SX;            // [tap][c][co] : (tap*8+c)*72+co

    __shared__ float s_mask[36];
    __shared__ float s_scale[64], s_shift[64];

    const int tid  = threadIdx.x;
    const int lane = tid & 31;
    const int wid  = tid >> 5;
    const int wm   = wid & 3;
    const int wn   = wid >> 2;
    const int lg   = lane >> 2;      // 0..7
    const int lt   = lane & 3;       // 0..3

    const int w0    = blockIdx.x * 16;
    const int h0    = blockIdx.y * 8;
    const int frame = blockIdx.z;
    const float* xf = x + (long)frame * FRAME_STRIDE;

    if (tid < 36) s_mask[tid] = mask[tid];
    if (tid < 64){ s_scale[tid] = g_bnscale[tid]; s_shift[tid] = g_bnshift[tid]; }

    float acc[2][4][4];
    #pragma unroll
    for (int mt=0;mt<2;mt++)
        #pragma unroll
        for (int nt=0;nt<4;nt++)
            #pragma unroll
            for (int r=0;r<4;r++) acc[mt][nt][r] = 0.f;

    for (int cg = 0; cg < 4; cg++){
        __syncthreads();   // previous cg's reads of s_x/s_b complete

        // ---- cp.async: all 9 taps of B for this cg (1152 16B chunks) ----
        for (int i = tid; i < 1152; i += 256){
            int q = i & 15;
            int c = (i >> 4) & 7;
            int j = i >> 7;
            uint32_t soff = (uint32_t)(((j*8 + c)*72 + q*4) * 4);
            long goff = ((long)(j*4 + cg)*8 + c)*64 + q*4;
            cp16(smem_u32(s_b) + soff, g_wf + goff);
        }
        asm volatile("cp.async.commit_group;" ::: "memory");

        // ---- halo stage (LDG + fp16 cvt + STS), overlaps cp.async ----
        for (int i = tid; i < 1600; i += 256){
            int c  = i / 200;
            int r2 = i - c*200;
            int yy = r2 / 20;
            int xx = r2 - yy*20;
            int gy = h0 + yy - 1, gx = w0 + xx - 1;
            float v0 = 0.f, v1 = 0.f;
            if (gy >= 0 && gy < H && gx >= 0 && gx < W){
                long base = (long)(cg*16 + 2*c)*(H*W) + gy*W + gx;
                v0 = xf[base];
                v1 = xf[base + H*W];
            }
            s_x[i] = packh2(__float2half_rn(v0), __float2half_rn(v1));
        }
        asm volatile("cp.async.wait_group 0;" ::: "memory");
        __syncthreads();

        // ---- 9 taps, no barriers ----
        #pragma unroll
        for (int tap = 0; tap < 9; tap++){
            const int ky = tap / 3, kx = tap - ky*3;
            uint32_t a[2][4], b[4][2];
            #pragma unroll
            for (int mt = 0; mt < 2; mt++){
                const int py = wm*2 + mt + ky;
                const int px = lg + kx;
                const int b0 = lt*200     + py*20 + px;
                const int b1 = (lt+4)*200 + py*20 + px;
                a[mt][0] = s_x[b0];
                a[mt][1] = s_x[b0 + 8];
                a[mt][2] = s_x[b1];
                a[mt][3] = s_x[b1 + 8];
            }
            #pragma unroll
            for (int nt = 0; nt < 4; nt++){
                const int co = wn*32 + nt*8 + lg;
                b[nt][0] = s_b[(tap*8 + lt  )*72 + co];
                b[nt][1] = s_b[(tap*8 + lt+4)*72 + co];
            }
            #pragma unroll
            for (int mt = 0; mt < 2; mt++)
                #pragma unroll
                for (int nt = 0; nt < 4; nt++)
                    mma_f16(acc[mt][nt], a[mt], b[nt]);
        }
    }

    // ---- epilogue: BN + GELU + mask -> patches (fp32) + fp16 A copy ----
    #pragma unroll
    for (int mt = 0; mt < 2; mt++){
        const int r0 = wm*32 + mt*16 + lg;
        #pragma unroll
        for (int dr = 0; dr < 2; dr++){
            const int r = r0 + dr*8;
            const int hh = h0 + (r >> 4);
            const int ww = w0 + (r & 15);
            const int l = hh / 6, i_in = hh - l*6;
            const int rr = ww / 6, j_in = ww - rr*6;
            const float mk = s_mask[i_in*6 + j_in];
            const long arow = ((long)frame*256 + l*16 + rr)*FEAT;
            #pragma unroll
            for (int nt = 0; nt < 4; nt++){
                const int c0 = wn*32 + nt*8 + (lt << 1);
                #pragma unroll
                for (int dc = 0; dc < 2; dc++){
                    const int co = c0 + dc;
                    const float v = acc[mt][nt][dr*2 + dc];
                    float o = gelu_exact(v*s_scale[co] + s_shift[co]) * mk;
                    const long k = arow + co*36 + i_in*6 + j_in;
                    out_patches[k] = o;
                    g_a16[k] = __float2half_rn(o);
                }
            }
        }
    }
}

// =====================================================================
// Kernel 2: tokens = gelu(A @ Wp^T + bias), fp16 m16n8k16 + cp.async
// (round-12 kernel, known good, unchanged)
// =====================================================================
#define GBM 128
#define GBN 64
#define GBK 64                      // fp16 elements per tile
#define KSTR 36                     // u32 words per row (32 data + 4 pad)
#define STAGES 3
#define SA_WORDS (GBM*KSTR)
#define SB_WORDS (GBN*KSTR)
#define GEMM_SMEM_BYTES ((STAGES*(SA_WORDS+SB_WORDS))*4)   // 82944

__global__ __launch_bounds__(256, 2) void gemm_tokens_f16_kernel(
    const float* __restrict__ bias,
    float* __restrict__ tok)
{
    extern __shared__ uint32_t smdyn[];
    uint32_t* s_a = smdyn;
    uint32_t* s_b = smdyn + STAGES*SA_WORDS;
    const uint32_t sa_base = smem_u32(s_a);
    const uint32_t sb_base = smem_u32(s_b);

    const int tid  = threadIdx.x;
    const int lane = tid & 31;
    const int wid  = tid >> 5;
    const int wm   = wid & 3;
    const int wn   = wid >> 2;
    const int bm   = blockIdx.y;
    const int bn   = blockIdx.x;

    const __half* Ab = g_a16 + (long)bm*GBM*FEAT;
    const __half* Bb = g_w16 + (long)bn*GBN*FEAT;

    float acc[2][4][4];
    #pragma unroll
    for (int mt=0;mt<2;mt++)
        #pragma unroll
        for (int nt=0;nt<4;nt++)
            #pragma unroll
            for (int r=0;r<4;r++) acc[mt][nt][r] = 0.f;

    const int crowA = tid >> 3;          // row base (j adds 32)
    const int ck4   = (tid & 7) << 2;    // u32 chunk offset within row
    const int ckh   = ck4 << 1;          // fp16 element offset

    #pragma unroll
    for (int st = 0; st < 2; st++){
        const int kg = st*GBK;
        #pragma unroll
        for (int j = 0; j < 4; j++){
            int row = crowA + j*32;
            cp16(sa_base + (uint32_t)((st*GBM + row)*KSTR + ck4)*4,
                 Ab + (long)row*FEAT + kg + ckh);
        }
        #pragma unroll
        for (int j = 0; j < 2; j++){
            int row = crowA + j*32;
            if (row < GBN)
                cp16(sb_base + (uint32_t)((st*GBN + row)*KSTR + ck4)*4,
                     Bb + (long)row*FEAT + kg + ckh);
        }
        asm volatile("cp.async.commit_group;");
    }
    asm volatile("cp.async.wait_group 1;");
    __syncthreads();

    const int NKT = FEAT / GBK;   // 36
    for (int kt = 0; kt < NKT; kt++){
        const int cur = kt % STAGES;
        if (kt + 2 < NKT){
            const int st = (kt + 2) % STAGES;
            const int kg = (kt + 2)*GBK;
            #pragma unroll
            for (int j = 0; j < 4; j++){
                int row = crowA + j*32;
                cp16(sa_base + (uint32_t)((st*GBM + row)*KSTR + ck4)*4,
                     Ab + (long)row*FEAT + kg + ckh);
            }
            #pragma unroll
            for (int j = 0; j < 2; j++){
                int row = crowA + j*32;
                if (row < GBN)
                    cp16(sb_base + (uint32_t)((st*GBN + row)*KSTR + ck4)*4,
                         Bb + (long)row*FEAT + kg + ckh);
            }
        }
        asm volatile("cp.async.commit_group;");

        const uint32_t* pa = s_a + cur*SA_WORDS;
        const uint32_t* pb = s_b + cur*SB_WORDS;
        #pragma unroll
        for (int ks = 0; ks < 4; ks++){
            const int kb = ks*8 + (lane & 3);   // k-pair index (16 fp16 per step)
            uint32_t af[2][4], bf[4][2];
            #pragma unroll
            for (int mt=0;mt<2;mt++){
                int r0 = wm*32 + mt*16 + (lane >> 2);
                af[mt][0] = pa[r0*KSTR + kb];
                af[mt][1] = pa[(r0+8)*KSTR + kb];
                af[mt][2] = pa[r0*KSTR + kb + 4];
                af[mt][3] = pa[(r0+8)*KSTR + kb + 4];
            }
            #pragma unroll
            for (int nt=0;nt<4;nt++){
                int c0 = wn*32 + nt*8 + (lane >> 2);
                bf[nt][0] = pb[c0*KSTR + kb];
                bf[nt][1] = pb[c0*KSTR + kb + 4];
            }
            #pragma unroll
            for (int mt=0;mt<2;mt++)
                #pragma unroll
                for (int nt=0;nt<4;nt++)
                    mma_f16(acc[mt][nt], af[mt], bf[nt]);
        }

        asm volatile("cp.async.wait_group 1;");
        __syncthreads();
    }

    #pragma unroll
    for (int mt=0;mt<2;mt++){
        const int r0 = bm*GBM + wm*32 + mt*16 + (lane >> 2);
        #pragma unroll
        for (int nt=0;nt<4;nt++){
            const int c0 = bn*GBN + wn*32 + nt*8 + ((lane & 3) << 1);
            float2 b2 = *(const float2*)(bias + c0);
            float2 o0, o1;
            o0.x = gelu_exact(acc[mt][nt][0] + b2.x);
            o0.y = gelu_exact(acc[mt][nt][1] + b2.y);
            o1.x = gelu_exact(acc[mt][nt][2] + b2.x);
            o1.y = gelu_exact(acc[mt][nt][3] + b2.y);
            *(float2*)(tok + (long)r0*DIM + c0)     = o0;
            *(float2*)(tok + (long)(r0+8)*DIM + c0) = o1;
        }
    }
}

// =====================================================================
extern "C" void kernel_launch(void* const* d_in, const int* in_sizes, int n_in,
                              void* d_out, int out_size)
{
    const float* x      = (const float*)d_in[0];
    const float* conv_w = (const float*)d_in[1];
    const float* conv_b = (const float*)d_in[2];
    const float* gamma  = (const float*)d_in[3];
    const float* beta   = (const float*)d_in[4];
    const float* mean   = (const float*)d_in[5];
    const float* var    = (const float*)d_in[6];
    const float* proj_w = (const float*)d_in[7];
    const float* proj_b = (const float*)d_in[8];
    const float* mask   = (const float*)d_in[9];

    float* tokens  = (float*)d_out;                 // [8192, 768]
    float* patches = (float*)d_out + TOK_ELEMS;     // [8192, 2304]

    cudaFuncSetAttribute(conv_mma_kernel,
                         cudaFuncAttributeMaxDynamicSharedMemorySize,
                         CV_SMEM_BYTES);
    cudaFuncSetAttribute(gemm_tokens_f16_kernel,
                         cudaFuncAttributeMaxDynamicSharedMemorySize,
                         GEMM_SMEM_BYTES);

    // 0) weight repack (fp16) + BN fold + proj_w fp16 convert
    prep_kernel<<<(DIM*FEAT + 255)/256, 256>>>(conv_w, conv_b, gamma, beta,
                                               mean, var, proj_w);

    // 1) conv as implicit GEMM (single-term fp16) -> patches + fp16 A copy
    {
        dim3 grid(W/16, H/8, NF);
        conv_mma_kernel<<<grid, 256, CV_SMEM_BYTES>>>(x, mask, patches);
    }

    // 2) projection GEMM + bias + GELU (fp16 m16n8k16, cp.async pipeline)
    {
        dim3 grid(DIM/GBN, M_TOK/GBM);
        gemm_tokens_f16_kernel<<<grid, 256, GEMM_SMEM_BYTES>>>(proj_b, tokens);
    }
}

// round 14
// speedup vs baseline: 2.3610x; 1.2821x over previous
#include <cuda_runtime.h>
#include <cuda_fp16.h>
#include <math.h>
#include <stdint.h>

// ---------------- problem constants ----------------
#define NF      32
#define C       64
#define H       96
#define W       96
#define FEAT    2304
#define DIM     768
#define M_TOK   (NF*256)                    // 8192
#define TOK_ELEMS   (M_TOK*DIM)
#define FRAME_STRIDE (C*H*W)

__device__ __forceinline__ float gelu_exact(float x){
    return 0.5f*x*(1.0f + erff(x*0.7071067811865476f));
}
__device__ __forceinline__ void mma_f16(float* d, const uint32_t* a, const uint32_t* b){
    asm volatile(
        "mma.sync.aligned.m16n8k16.row.col.f32.f16.f16.f32 "
        "{%0,%1,%2,%3}, {%4,%5,%6,%7}, {%8,%9}, {%0,%1,%2,%3};"
        : "+f"(d[0]), "+f"(d[1]), "+f"(d[2]), "+f"(d[3])
        : "r"(a[0]), "r"(a[1]), "r"(a[2]), "r"(a[3]), "r"(b[0]), "r"(b[1]));
}
__device__ __forceinline__ void cp16(uint32_t saddr, const void* g){
    asm volatile("cp.async.cg.shared.global [%0], [%1], 16;" :: "r"(saddr), "l"(g));
}
__device__ __forceinline__ uint32_t packh2(__half a, __half b){
    uint32_t lo = (uint32_t)__half_as_ushort(a);
    uint32_t hi = (uint32_t)__half_as_ushort(b);
    return (hi << 16) | lo;
}
__device__ __forceinline__ uint32_t smem_u32(const void* p){
    return (uint32_t)__cvta_generic_to_shared(p);
}

// ---------------- device globals ----------------
__device__ uint32_t g_wf[9*4*8*64];      // conv weights fp16x2 [tap][cg][ci-pair][co]
__device__ float g_bnscale[64];
__device__ float g_bnshift[64];
__device__ __half g_w16[DIM*FEAT];       // proj_w fp16
__device__ __half g_a16[(long)M_TOK*FEAT]; // masked patches fp16

// =====================================================================
// Kernel 0: conv-weight fp16 repack + BN fold + proj_w fp16 convert
// =====================================================================
__global__ void prep_kernel(const float* __restrict__ cw,
                            const float* __restrict__ cb,
                            const float* __restrict__ gamma,
                            const float* __restrict__ beta,
                            const float* __restrict__ mean,
                            const float* __restrict__ var,
                            const float* __restrict__ pw)
{
    int idx = blockIdx.x*256 + threadIdx.x;
    if (idx < 9*4*8*64){
        int co  = idx & 63;
        int c   = (idx >> 6) & 7;
        int cg  = (idx >> 9) & 3;
        int tap = idx >> 11;
        int ci0 = cg*16 + 2*c;
        float w0 = cw[(co*64 + ci0)*9 + tap];
        float w1 = cw[(co*64 + ci0 + 1)*9 + tap];
        g_wf[idx] = packh2(__float2half_rn(w0), __float2half_rn(w1));
    }
    if (idx < DIM*FEAT)
        g_w16[idx] = __float2half_rn(pw[idx]);
    if (blockIdx.x == 0 && threadIdx.x < 64){
        int co = threadIdx.x;
        float s = gamma[co] * rsqrtf(var[co] + 1e-5f);
        g_bnscale[co] = s;
        g_bnshift[co] = (cb[co] - mean[co]) * s + beta[co];
    }
}

// =====================================================================
// Kernel 1: conv3x3 implicit GEMM, single-term fp16 mma, SW-PIPELINED:
// cg+1's B (cp.async) and halo (LDG->regs) issued before cg's 9-tap
// mma loop; committed after. 1 barrier per cg, load latency hidden.
// =====================================================================
#define CV_SX 1600                 // 8 ci-pairs x 10 y x 20 x (stride 200)
#define CV_SB (9*8*72)             // 9 taps x 8 ci-pairs x co (pad 72)
#define CV_SMEM_BYTES ((2*CV_SX + 2*CV_SB)*4)   // 33,536

__global__ __launch_bounds__(256, 2) void conv_mma_kernel(
    const float* __restrict__ x,
    const float* __restrict__ mask,
    float* __restrict__ out_patches)
{
    extern __shared__ __align__(16) uint32_t dynsm[];
    uint32_t* s_x = dynsm;                     // [buf][c][y][x]
    uint32_t* s_b = dynsm + 2*CV_SX;           // [buf][tap][c][co]

    __shared__ float s_mask[36];
    __shared__ float s_scale[64], s_shift[64];

    const int tid  = threadIdx.x;
    const int lane = tid & 31;
    const int wid  = tid >> 5;
    const int wm   = wid & 3;
    const int wn   = wid >> 2;
    const int lg   = lane >> 2;      // 0..7
    const int lt   = lane & 3;       // 0..3

    const int w0    = blockIdx.x * 16;
    const int h0    = blockIdx.y * 8;
    const int frame = blockIdx.z;
    const float* xf = x + (long)frame * FRAME_STRIDE;

    if (tid < 36) s_mask[tid] = mask[tid];
    if (tid < 64){ s_scale[tid] = g_bnscale[tid]; s_shift[tid] = g_bnshift[tid]; }

    // precomputed halo-staging geometry for this thread (7 slots)
    int hg_y[7], hg_x[7], hg_c[7];
    bool hg_ok[7];
    #pragma unroll
    for (int j = 0; j < 7; j++){
        int i = tid + j*256;
        bool valid = (i < 1600);
        int c  = valid ? i / 200 : 0;
        int r2 = valid ? i - c*200 : 0;
        int yy = r2 / 20;
        int xx = r2 - yy*20;
        hg_c[j] = c;
        hg_y[j] = h0 + yy - 1;
        hg_x[j] = w0 + xx - 1;
        hg_ok[j] = valid && hg_y[j] >= 0 && hg_y[j] < H && hg_x[j] >= 0 && hg_x[j] < W;
    }

    float acc[2][4][4];
    #pragma unroll
    for (int mt=0;mt<2;mt++)
        #pragma unroll
        for (int nt=0;nt<4;nt++)
            #pragma unroll
            for (int r=0;r<4;r++) acc[mt][nt][r] = 0.f;

    // ---- prologue: stage cg=0 into buffer 0 ----
    for (int i = tid; i < 1152; i += 256){
        int q = i & 15;
        int c = (i >> 4) & 7;
        int j = i >> 7;
        cp16(smem_u32(s_b) + (uint32_t)(((j*8 + c)*72 + q*4) * 4),
             g_wf + (((long)(j*4 + 0)*8 + c)*64 + q*4));
    }
    asm volatile("cp.async.commit_group;" ::: "memory");
    #pragma unroll
    for (int j = 0; j < 7; j++){
        int i = tid + j*256;
        if (i < 1600){
            float v0 = 0.f, v1 = 0.f;
            if (hg_ok[j]){
                long base = (long)(2*hg_c[j])*(H*W) + hg_y[j]*W + hg_x[j];
                v0 = xf[base];
                v1 = xf[base + H*W];
            }
            s_x[i] = packh2(__float2half_rn(v0), __float2half_rn(v1));
        }
    }
    asm volatile("cp.async.wait_group 0;" ::: "memory");
    __syncthreads();

    for (int cg = 0; cg < 4; cg++){
        const int cur = cg & 1;
        const int nxt = cur ^ 1;
        const bool hasnext = (cg < 3);
        const uint32_t* px_ = s_x + cur*CV_SX;
        const uint32_t* pb_ = s_b + cur*CV_SB;

        // ---- issue next cg's B (cp.async) + halo (LDG into regs) ----
        float nv0[7], nv1[7];
        if (hasnext){
            for (int i = tid; i < 1152; i += 256){
                int q = i & 15;
                int c = (i >> 4) & 7;
                int j = i >> 7;
                cp16(smem_u32(s_b + nxt*CV_SB) + (uint32_t)(((j*8 + c)*72 + q*4) * 4),
                     g_wf + (((long)(j*4 + cg + 1)*8 + c)*64 + q*4));
            }
            asm volatile("cp.async.commit_group;" ::: "memory");
            const int cbase = (cg + 1)*16;
            #pragma unroll
            for (int j = 0; j < 7; j++){
                nv0[j] = 0.f; nv1[j] = 0.f;
                if (hg_ok[j]){
                    long base = (long)(cbase + 2*hg_c[j])*(H*W) + hg_y[j]*W + hg_x[j];
                    nv0[j] = xf[base];
                    nv1[j] = xf[base + H*W];
                }
            }
        }

        // ---- 9 taps on current buffer ----
        #pragma unroll
        for (int tap = 0; tap < 9; tap++){
            const int ky = tap / 3, kx = tap - ky*3;
            uint32_t a[2][4], b[4][2];
            #pragma unroll
            for (int mt = 0; mt < 2; mt++){
                const int py = wm*2 + mt + ky;
                const int pxi = lg + kx;
                const int b0 = lt*200     + py*20 + pxi;
                const int b1 = (lt+4)*200 + py*20 + pxi;
                a[mt][0] = px_[b0];
                a[mt][1] = px_[b0 + 8];
                a[mt][2] = px_[b1];
                a[mt][3] = px_[b1 + 8];
            }
            #pragma unroll
            for (int nt = 0; nt < 4; nt++){
                const int co = wn*32 + nt*8 + lg;
                b[nt][0] = pb_[(tap*8 + lt  )*72 + co];
                b[nt][1] = pb_[(tap*8 + lt+4)*72 + co];
            }
            #pragma unroll
            for (int mt = 0; mt < 2; mt++)
                #pragma unroll
                for (int nt = 0; nt < 4; nt++)
                    mma_f16(acc[mt][nt], a[mt], b[nt]);
        }

        // ---- commit next halo, wait B, flip ----
        if (hasnext){
            uint32_t* dx = s_x + nxt*CV_SX;
            #pragma unroll
            for (int j = 0; j < 7; j++){
                int i = tid + j*256;
                if (i < 1600)
                    dx[i] = packh2(__float2half_rn(nv0[j]), __float2half_rn(nv1[j]));
            }
            asm volatile("cp.async.wait_group 0;" ::: "memory");
            __syncthreads();
        }
    }

    // ---- epilogue: BN + GELU + mask -> patches (fp32) + fp16 A copy ----
    #pragma unroll
    for (int mt = 0; mt < 2; mt++){
        const int r0 = wm*32 + mt*16 + lg;
        #pragma unroll
        for (int dr = 0; dr < 2; dr++){
            const int r = r0 + dr*8;
            const int hh = h0 + (r >> 4);
            const int ww = w0 + (r & 15);
            const int l = hh / 6, i_in = hh - l*6;
            const int rr = ww / 6, j_in = ww - rr*6;
            const float mk = s_mask[i_in*6 + j_in];
            const long arow = ((long)frame*256 + l*16 + rr)*FEAT;
            #pragma unroll
            for (int nt = 0; nt < 4; nt++){
                const int c0 = wn*32 + nt*8 + (lt << 1);
                #pragma unroll
                for (int dc = 0; dc < 2; dc++){
                    const int co = c0 + dc;
                    const float v = acc[mt][nt][dr*2 + dc];
                    float o = gelu_exact(v*s_scale[co] + s_shift[co]) * mk;
                    const long k = arow + co*36 + i_in*6 + j_in;
                    out_patches[k] = o;
                    g_a16[k] = __float2half_rn(o);
                }
            }
        }
    }
}

// =====================================================================
// Kernel 2: tokens = gelu(A @ Wp^T + bias), fp16 m16n8k16 + cp.async
// (round-12 kernel, known good, unchanged)
// =====================================================================
#define GBM 128
#define GBN 64
#define GBK 64                      // fp16 elements per tile
#define KSTR 36                     // u32 words per row (32 data + 4 pad)
#define STAGES 3
#define SA_WORDS (GBM*KSTR)
#define SB_WORDS (GBN*KSTR)
#define GEMM_SMEM_BYTES ((STAGES*(SA_WORDS+SB_WORDS))*4)   // 82944

__global__ __launch_bounds__(256, 2) void gemm_tokens_f16_kernel(
    const float* __restrict__ bias,
    float* __restrict__ tok)
{
    extern __shared__ uint32_t smdyn[];
    uint32_t* s_a = smdyn;
    uint32_t* s_b = smdyn + STAGES*SA_WORDS;
    const uint32_t sa_base = smem_u32(s_a);
    const uint32_t sb_base = smem_u32(s_b);

    const int tid  = threadIdx.x;
    const int lane = tid & 31;
    const int wid  = tid >> 5;
    const int wm   = wid & 3;
    const int wn   = wid >> 2;
    const int bm   = blockIdx.y;
    const int bn   = blockIdx.x;

    const __half* Ab = g_a16 + (long)bm*GBM*FEAT;
    const __half* Bb = g_w16 + (long)bn*GBN*FEAT;

    float acc[2][4][4];
    #pragma unroll
    for (int mt=0;mt<2;mt++)
        #pragma unroll
        for (int nt=0;nt<4;nt++)
            #pragma unroll
            for (int r=0;r<4;r++) acc[mt][nt][r] = 0.f;

    const int crowA = tid >> 3;          // row base (j adds 32)
    const int ck4   = (tid & 7) << 2;    // u32 chunk offset within row
    const int ckh   = ck4 << 1;          // fp16 element offset

    #pragma unroll
    for (int st = 0; st < 2; st++){
        const int kg = st*GBK;
        #pragma unroll
        for (int j = 0; j < 4; j++){
            int row = crowA + j*32;
            cp16(sa_base + (uint32_t)((st*GBM + row)*KSTR + ck4)*4,
                 Ab + (long)row*FEAT + kg + ckh);
        }
        #pragma unroll
        for (int j = 0; j < 2; j++){
            int row = crowA + j*32;
            if (row < GBN)
                cp16(sb_base + (uint32_t)((st*GBN + row)*KSTR + ck4)*4,
                     Bb + (long)row*FEAT + kg + ckh);
        }
        asm volatile("cp.async.commit_group;");
    }
    asm volatile("cp.async.wait_group 1;");
    __syncthreads();

    const int NKT = FEAT / GBK;   // 36
    for (int kt = 0; kt < NKT; kt++){
        const int cur = kt % STAGES;
        if (kt + 2 < NKT){
            const int st = (kt + 2) % STAGES;
            const int kg = (kt + 2)*GBK;
            #pragma unroll
            for (int j = 0; j < 4; j++){
                int row = crowA + j*32;
                cp16(sa_base + (uint32_t)((st*GBM + row)*KSTR + ck4)*4,
                     Ab + (long)row*FEAT + kg + ckh);
            }
            #pragma unroll
            for (int j = 0; j < 2; j++){
                int row = crowA + j*32;
                if (row < GBN)
                    cp16(sb_base + (uint32_t)((st*GBN + row)*KSTR + ck4)*4,
                         Bb + (long)row*FEAT + kg + ckh);
            }
        }
        asm volatile("cp.async.commit_group;");

        const uint32_t* pa = s_a + cur*SA_WORDS;
        const uint32_t* pb = s_b + cur*SB_WORDS;
        #pragma unroll
        for (int ks = 0; ks < 4; ks++){
            const int kb = ks*8 + (lane & 3);   // k-pair index (16 fp16 per step)
            uint32_t af[2][4], bf[4][2];
            #pragma unroll
            for (int mt=0;mt<2;mt++){
                int r0 = wm*32 + mt*16 + (lane >> 2);
                af[mt][0] = pa[r0*KSTR + kb];
                af[mt][1] = pa[(r0+8)*KSTR + kb];
                af[mt][2] = pa[r0*KSTR + kb + 4];
                af[mt][3] = pa[(r0+8)*KSTR + kb + 4];
            }
            #pragma unroll
            for (int nt=0;nt<4;nt++){
                int c0 = wn*32 + nt*8 + (lane >> 2);
                bf[nt][0] = pb[c0*KSTR + kb];
                bf[nt][1] = pb[c0*KSTR + kb + 4];
            }
            #pragma unroll
            for (int mt=0;mt<2;mt++)
                #pragma unroll
                for (int nt=0;nt<4;nt++)
                    mma_f16(acc[mt][nt], af[mt], bf[nt]);
        }

        asm volatile("cp.async.wait_group 1;");
        __syncthreads();
    }

    #pragma unroll
    for (int mt=0;mt<2;mt++){
        const int r0 = bm*GBM + wm*32 + mt*16 + (lane >> 2);
        #pragma unroll
        for (int nt=0;nt<4;nt++){
            const int c0 = bn*GBN + wn*32 + nt*8 + ((lane & 3) << 1);
            float2 b2 = *(const float2*)(bias + c0);
            float2 o0, o1;
            o0.x = gelu_exact(acc[mt][nt][0] + b2.x);
            o0.y = gelu_exact(acc[mt][nt][1] + b2.y);
            o1.x = gelu_exact(acc[mt][nt][2] + b2.x);
            o1.y = gelu_exact(acc[mt][nt][3] + b2.y);
            *(float2*)(tok + (long)r0*DIM + c0)     = o0;
            *(float2*)(tok + (long)(r0+8)*DIM + c0) = o1;
        }
    }
}

// =====================================================================
extern "C" void kernel_launch(void* const* d_in, const int* in_sizes, int n_in,
                              void* d_out, int out_size)
{
    const float* x      = (const float*)d_in[0];
    const float* conv_w = (const float*)d_in[1];
    const float* conv_b = (const float*)d_in[2];
    const float* gamma  = (const float*)d_in[3];
    const float* beta   = (const float*)d_in[4];
    const float* mean   = (const float*)d_in[5];
    const float* var    = (const float*)d_in[6];
    const float* proj_w = (const float*)d_in[7];
    const float* proj_b = (const float*)d_in[8];
    const float* mask   = (const float*)d_in[9];

    float* tokens  = (float*)d_out;                 // [8192, 768]
    float* patches = (float*)d_out + TOK_ELEMS;     // [8192, 2304]

    cudaFuncSetAttribute(conv_mma_kernel,
                         cudaFuncAttributeMaxDynamicSharedMemorySize,
                         CV_SMEM_BYTES);
    cudaFuncSetAttribute(gemm_tokens_f16_kernel,
                         cudaFuncAttributeMaxDynamicSharedMemorySize,
                         GEMM_SMEM_BYTES);

    // 0) weight repack (fp16) + BN fold + proj_w fp16 convert
    prep_kernel<<<(DIM*FEAT + 255)/256, 256>>>(conv_w, conv_b, gamma, beta,
                                               mean, var, proj_w);

    // 1) conv as implicit GEMM (single-term fp16, sw-pipelined)
    {
        dim3 grid(W/16, H/8, NF);
        conv_mma_kernel<<<grid, 256, CV_SMEM_BYTES>>>(x, mask, patches);
    }

    // 2) projection GEMM + bias + GELU (fp16 m16n8k16, cp.async pipeline)
    {
        dim3 grid(DIM/GBN, M_TOK/GBM);
        gemm_tokens_f16_kernel<<<grid, 256, GEMM_SMEM_BYTES>>>(proj_b, tokens);
    }
}

// round 15
// speedup vs baseline: 2.4976x; 1.0579x over previous
#include <cuda_runtime.h>
#include <cuda_fp16.h>
#include <math.h>
#include <stdint.h>

// ---------------- problem constants ----------------
#define NF      32
#define C       64
#define H       96
#define W       96
#define FEAT    2304
#define DIM     768
#define M_TOK   (NF*256)                    // 8192
#define TOK_ELEMS   (M_TOK*DIM)
#define FRAME_STRIDE (C*H*W)

__device__ __forceinline__ float gelu_exact(float x){
    return 0.5f*x*(1.0f + erff(x*0.7071067811865476f));
}
__device__ __forceinline__ void mma_f16(float* d, const uint32_t* a, const uint32_t* b){
    asm volatile(
        "mma.sync.aligned.m16n8k16.row.col.f32.f16.f16.f32 "
        "{%0,%1,%2,%3}, {%4,%5,%6,%7}, {%8,%9}, {%0,%1,%2,%3};"
        : "+f"(d[0]), "+f"(d[1]), "+f"(d[2]), "+f"(d[3])
        : "r"(a[0]), "r"(a[1]), "r"(a[2]), "r"(a[3]), "r"(b[0]), "r"(b[1]));
}
__device__ __forceinline__ void cp16(uint32_t saddr, const void* g){
    asm volatile("cp.async.cg.shared.global [%0], [%1], 16;" :: "r"(saddr), "l"(g));
}
__device__ __forceinline__ uint32_t packh2(__half a, __half b){
    uint32_t lo = (uint32_t)__half_as_ushort(a);
    uint32_t hi = (uint32_t)__half_as_ushort(b);
    return (hi << 16) | lo;
}
__device__ __forceinline__ uint32_t smem_u32(const void* p){
    return (uint32_t)__cvta_generic_to_shared(p);
}

// ---------------- device globals ----------------
__device__ uint32_t g_wf[9*4*8*64];      // conv weights fp16x2 [tap][cg][ci-pair][co]
__device__ float g_bnscale[64];
__device__ float g_bnshift[64];
__device__ __half g_w16[DIM*FEAT];       // proj_w fp16
__device__ __half g_a16[(long)M_TOK*FEAT]; // masked patches fp16

// =====================================================================
// Kernel 0: conv-weight fp16 repack + BN fold + proj_w fp16 convert
// =====================================================================
__global__ void prep_kernel(const float* __restrict__ cw,
                            const float* __restrict__ cb,
                            const float* __restrict__ gamma,
                            const float* __restrict__ beta,
                            const float* __restrict__ mean,
                            const float* __restrict__ var,
                            const float* __restrict__ pw)
{
    int idx = blockIdx.x*256 + threadIdx.x;
    if (idx < 9*4*8*64){
        int co  = idx & 63;
        int c   = (idx >> 6) & 7;
        int cg  = (idx >> 9) & 3;
        int tap = idx >> 11;
        int ci0 = cg*16 + 2*c;
        float w0 = cw[(co*64 + ci0)*9 + tap];
        float w1 = cw[(co*64 + ci0 + 1)*9 + tap];
        g_wf[idx] = packh2(__float2half_rn(w0), __float2half_rn(w1));
    }
    if (idx < DIM*FEAT)
        g_w16[idx] = __float2half_rn(pw[idx]);
    if (blockIdx.x == 0 && threadIdx.x < 64){
        int co = threadIdx.x;
        float s = gamma[co] * rsqrtf(var[co] + 1e-5f);
        g_bnscale[co] = s;
        g_bnshift[co] = (cb[co] - mean[co]) * s + beta[co];
    }
}

// =====================================================================
// Kernel 1: conv3x3 implicit GEMM, single-term fp16 mma, sw-pipelined
// (round-14 kernel, known good, unchanged)
// =====================================================================
#define CV_SX 1600                 // 8 ci-pairs x 10 y x 20 x (stride 200)
#define CV_SB (9*8*72)             // 9 taps x 8 ci-pairs x co (pad 72)
#define CV_SMEM_BYTES ((2*CV_SX + 2*CV_SB)*4)   // 33,536

__global__ __launch_bounds__(256, 2) void conv_mma_kernel(
    const float* __restrict__ x,
    const float* __restrict__ mask,
    float* __restrict__ out_patches)
{
    extern __shared__ __align__(16) uint32_t dynsm[];
    uint32_t* s_x = dynsm;                     // [buf][c][y][x]
    uint32_t* s_b = dynsm + 2*CV_SX;           // [buf][tap][c][co]

    __shared__ float s_mask[36];
    __shared__ float s_scale[64], s_shift[64];

    const int tid  = threadIdx.x;
    const int lane = tid & 31;
    const int wid  = tid >> 5;
    const int wm   = wid & 3;
    const int wn   = wid >> 2;
    const int lg   = lane >> 2;      // 0..7
    const int lt   = lane & 3;       // 0..3

    const int w0    = blockIdx.x * 16;
    const int h0    = blockIdx.y * 8;
    const int frame = blockIdx.z;
    const float* xf = x + (long)frame * FRAME_STRIDE;

    if (tid < 36) s_mask[tid] = mask[tid];
    if (tid < 64){ s_scale[tid] = g_bnscale[tid]; s_shift[tid] = g_bnshift[tid]; }

    int hg_y[7], hg_x[7], hg_c[7];
    bool hg_ok[7];
    #pragma unroll
    for (int j = 0; j < 7; j++){
        int i = tid + j*256;
        bool valid = (i < 1600);
        int c  = valid ? i / 200 : 0;
        int r2 = valid ? i - c*200 : 0;
        int yy = r2 / 20;
        int xx = r2 - yy*20;
        hg_c[j] = c;
        hg_y[j] = h0 + yy - 1;
        hg_x[j] = w0 + xx - 1;
        hg_ok[j] = valid && hg_y[j] >= 0 && hg_y[j] < H && hg_x[j] >= 0 && hg_x[j] < W;
    }

    float acc[2][4][4];
    #pragma unroll
    for (int mt=0;mt<2;mt++)
        #pragma unroll
        for (int nt=0;nt<4;nt++)
            #pragma unroll
            for (int r=0;r<4;r++) acc[mt][nt][r] = 0.f;

    // ---- prologue: stage cg=0 into buffer 0 ----
    for (int i = tid; i < 1152; i += 256){
        int q = i & 15;
        int c = (i >> 4) & 7;
        int j = i >> 7;
        cp16(smem_u32(s_b) + (uint32_t)(((j*8 + c)*72 + q*4) * 4),
             g_wf + (((long)(j*4 + 0)*8 + c)*64 + q*4));
    }
    asm volatile("cp.async.commit_group;" ::: "memory");
    #pragma unroll
    for (int j = 0; j < 7; j++){
        int i = tid + j*256;
        if (i < 1600){
            float v0 = 0.f, v1 = 0.f;
            if (hg_ok[j]){
                long base = (long)(2*hg_c[j])*(H*W) + hg_y[j]*W + hg_x[j];
                v0 = xf[base];
                v1 = xf[base + H*W];
            }
            s_x[i] = packh2(__float2half_rn(v0), __float2half_rn(v1));
        }
    }
    asm volatile("cp.async.wait_group 0;" ::: "memory");
    __syncthreads();

    for (int cg = 0; cg < 4; cg++){
        const int cur = cg & 1;
        const int nxt = cur ^ 1;
        const bool hasnext = (cg < 3);
        const uint32_t* px_ = s_x + cur*CV_SX;
        const uint32_t* pb_ = s_b + cur*CV_SB;

        float nv0[7], nv1[7];
        if (hasnext){
            for (int i = tid; i < 1152; i += 256){
                int q = i & 15;
                int c = (i >> 4) & 7;
                int j = i >> 7;
                cp16(smem_u32(s_b + nxt*CV_SB) + (uint32_t)(((j*8 + c)*72 + q*4) * 4),
                     g_wf + (((long)(j*4 + cg + 1)*8 + c)*64 + q*4));
            }
            asm volatile("cp.async.commit_group;" ::: "memory");
            const int cbase = (cg + 1)*16;
            #pragma unroll
            for (int j = 0; j < 7; j++){
                nv0[j] = 0.f; nv1[j] = 0.f;
                if (hg_ok[j]){
                    long base = (long)(cbase + 2*hg_c[j])*(H*W) + hg_y[j]*W + hg_x[j];
                    nv0[j] = xf[base];
                    nv1[j] = xf[base + H*W];
                }
            }
        }

        #pragma unroll
        for (int tap = 0; tap < 9; tap++){
            const int ky = tap / 3, kx = tap - ky*3;
            uint32_t a[2][4], b[4][2];
            #pragma unroll
            for (int mt = 0; mt < 2; mt++){
                const int py = wm*2 + mt + ky;
                const int pxi = lg + kx;
                const int b0 = lt*200     + py*20 + pxi;
                const int b1 = (lt+4)*200 + py*20 + pxi;
                a[mt][0] = px_[b0];
                a[mt][1] = px_[b0 + 8];
                a[mt][2] = px_[b1];
                a[mt][3] = px_[b1 + 8];
            }
            #pragma unroll
            for (int nt = 0; nt < 4; nt++){
                const int co = wn*32 + nt*8 + lg;
                b[nt][0] = pb_[(tap*8 + lt  )*72 + co];
                b[nt][1] = pb_[(tap*8 + lt+4)*72 + co];
            }
            #pragma unroll
            for (int mt = 0; mt < 2; mt++)
                #pragma unroll
                for (int nt = 0; nt < 4; nt++)
                    mma_f16(acc[mt][nt], a[mt], b[nt]);
        }

        if (hasnext){
            uint32_t* dx = s_x + nxt*CV_SX;
            #pragma unroll
            for (int j = 0; j < 7; j++){
                int i = tid + j*256;
                if (i < 1600)
                    dx[i] = packh2(__float2half_rn(nv0[j]), __float2half_rn(nv1[j]));
            }
            asm volatile("cp.async.wait_group 0;" ::: "memory");
            __syncthreads();
        }
    }

    #pragma unroll
    for (int mt = 0; mt < 2; mt++){
        const int r0 = wm*32 + mt*16 + lg;
        #pragma unroll
        for (int dr = 0; dr < 2; dr++){
            const int r = r0 + dr*8;
            const int hh = h0 + (r >> 4);
            const int ww = w0 + (r & 15);
            const int l = hh / 6, i_in = hh - l*6;
            const int rr = ww / 6, j_in = ww - rr*6;
            const float mk = s_mask[i_in*6 + j_in];
            const long arow = ((long)frame*256 + l*16 + rr)*FEAT;
            #pragma unroll
            for (int nt = 0; nt < 4; nt++){
                const int c0 = wn*32 + nt*8 + (lt << 1);
                #pragma unroll
                for (int dc = 0; dc < 2; dc++){
                    const int co = c0 + dc;
                    const float v = acc[mt][nt][dr*2 + dc];
                    float o = gelu_exact(v*s_scale[co] + s_shift[co]) * mk;
                    const long k = arow + co*36 + i_in*6 + j_in;
                    out_patches[k] = o;
                    g_a16[k] = __float2half_rn(o);
                }
            }
        }
    }
}

// =====================================================================
// Kernel 2: tokens GEMM, fp16 m16n8k16 + cp.async. Warp tile widened to
// 32x48 (nt=6): 12 independent acc chains, LDS/mma 1.17. Block 128x96.
// =====================================================================
#define GBM 128
#define GBN 96
#define GBK 64                      // fp16 elements per tile
#define KSTR 36                     // u32 words per row (32 data + 4 pad)
#define STAGES 3
#define SA_WORDS (GBM*KSTR)
#define SB_WORDS (GBN*KSTR)
#define GEMM_SMEM_BYTES ((STAGES*(SA_WORDS+SB_WORDS))*4)   // 96768

__global__ __launch_bounds__(256, 2) void gemm_tokens_f16_kernel(
    const float* __restrict__ bias,
    float* __restrict__ tok)
{
    extern __shared__ uint32_t smdyn[];
    uint32_t* s_a = smdyn;
    uint32_t* s_b = smdyn + STAGES*SA_WORDS;
    const uint32_t sa_base = smem_u32(s_a);
    const uint32_t sb_base = smem_u32(s_b);

    const int tid  = threadIdx.x;
    const int lane = tid & 31;
    const int wid  = tid >> 5;
    const int wm   = wid & 3;       // 4 m-warps (32 rows each)
    const int wn   = wid >> 2;      // 2 n-warps (48 cols each)
    const int bm   = blockIdx.y;
    const int bn   = blockIdx.x;

    const __half* Ab = g_a16 + (long)bm*GBM*FEAT;
    const __half* Bb = g_w16 + (long)bn*GBN*FEAT;

    float acc[2][6][4];
    #pragma unroll
    for (int mt=0;mt<2;mt++)
        #pragma unroll
        for (int nt=0;nt<6;nt++)
            #pragma unroll
            for (int r=0;r<4;r++) acc[mt][nt][r] = 0.f;

    const int crowA = tid >> 3;          // row base (j adds 32)
    const int ck4   = (tid & 7) << 2;    // u32 chunk offset within row
    const int ckh   = ck4 << 1;          // fp16 element offset

    #pragma unroll
    for (int st = 0; st < 2; st++){
        const int kg = st*GBK;
        #pragma unroll
        for (int j = 0; j < 4; j++){
            int row = crowA + j*32;
            cp16(sa_base + (uint32_t)((st*GBM + row)*KSTR + ck4)*4,
                 Ab + (long)row*FEAT + kg + ckh);
        }
        #pragma unroll
        for (int j = 0; j < 3; j++){
            int row = crowA + j*32;
            cp16(sb_base + (uint32_t)((st*GBN + row)*KSTR + ck4)*4,
                 Bb + (long)row*FEAT + kg + ckh);
        }
        asm volatile("cp.async.commit_group;");
    }
    asm volatile("cp.async.wait_group 1;");
    __syncthreads();

    const int NKT = FEAT / GBK;   // 36
    for (int kt = 0; kt < NKT; kt++){
        const int cur = kt % STAGES;
        if (kt + 2 < NKT){
            const int st = (kt + 2) % STAGES;
            const int kg = (kt + 2)*GBK;
            #pragma unroll
            for (int j = 0; j < 4; j++){
                int row = crowA + j*32;
                cp16(sa_base + (uint32_t)((st*GBM + row)*KSTR + ck4)*4,
                     Ab + (long)row*FEAT + kg + ckh);
            }
            #pragma unroll
            for (int j = 0; j < 3; j++){
                int row = crowA + j*32;
                cp16(sb_base + (uint32_t)((st*GBN + row)*KSTR + ck4)*4,
                     Bb + (long)row*FEAT + kg + ckh);
            }
        }
        asm volatile("cp.async.commit_group;");

        const uint32_t* pa = s_a + cur*SA_WORDS;
        const uint32_t* pb = s_b + cur*SB_WORDS;
        #pragma unroll
        for (int ks = 0; ks < 4; ks++){
            const int kb = ks*8 + (lane & 3);   // k-pair index (16 fp16 per step)
            uint32_t af[2][4], bf[6][2];
            #pragma unroll
            for (int mt=0;mt<2;mt++){
                int r0 = wm*32 + mt*16 + (lane >> 2);
                af[mt][0] = pa[r0*KSTR + kb];
                af[mt][1] = pa[(r0+8)*KSTR + kb];
                af[mt][2] = pa[r0*KSTR + kb + 4];
                af[mt][3] = pa[(r0+8)*KSTR + kb + 4];
            }
            #pragma unroll
            for (int nt=0;nt<6;nt++){
                int c0 = wn*48 + nt*8 + (lane >> 2);
                bf[nt][0] = pb[c0*KSTR + kb];
                bf[nt][1] = pb[c0*KSTR + kb + 4];
            }
            #pragma unroll
            for (int mt=0;mt<2;mt++)
                #pragma unroll
                for (int nt=0;nt<6;nt++)
                    mma_f16(acc[mt][nt], af[mt], bf[nt]);
        }

        asm volatile("cp.async.wait_group 1;");
        __syncthreads();
    }

    #pragma unroll
    for (int mt=0;mt<2;mt++){
        const int r0 = bm*GBM + wm*32 + mt*16 + (lane >> 2);
        #pragma unroll
        for (int nt=0;nt<6;nt++){
            const int c0 = bn*GBN + wn*48 + nt*8 + ((lane & 3) << 1);
            float2 b2 = *(const float2*)(bias + c0);
            float2 o0, o1;
            o0.x = gelu_exact(acc[mt][nt][0] + b2.x);
            o0.y = gelu_exact(acc[mt][nt][1] + b2.y);
            o1.x = gelu_exact(acc[mt][nt][2] + b2.x);
            o1.y = gelu_exact(acc[mt][nt][3] + b2.y);
            *(float2*)(tok + (long)r0*DIM + c0)     = o0;
            *(float2*)(tok + (long)(r0+8)*DIM + c0) = o1;
        }
    }
}

// =====================================================================
extern "C" void kernel_launch(void* const* d_in, const int* in_sizes, int n_in,
                              void* d_out, int out_size)
{
    const float* x      = (const float*)d_in[0];
    const float* conv_w = (const float*)d_in[1];
    const float* conv_b = (const float*)d_in[2];
    const float* gamma  = (const float*)d_in[3];
    const float* beta   = (const float*)d_in[4];
    const float* mean   = (const float*)d_in[5];
    const float* var    = (const float*)d_in[6];
    const float* proj_w = (const float*)d_in[7];
    const float* proj_b = (const float*)d_in[8];
    const float* mask   = (const float*)d_in[9];

    float* tokens  = (float*)d_out;                 // [8192, 768]
    float* patches = (float*)d_out + TOK_ELEMS;     // [8192, 2304]

    cudaFuncSetAttribute(conv_mma_kernel,
                         cudaFuncAttributeMaxDynamicSharedMemorySize,
                         CV_SMEM_BYTES);
    cudaFuncSetAttribute(gemm_tokens_f16_kernel,
                         cudaFuncAttributeMaxDynamicSharedMemorySize,
                         GEMM_SMEM_BYTES);

    // 0) weight repack (fp16) + BN fold + proj_w fp16 convert
    prep_kernel<<<(DIM*FEAT + 255)/256, 256>>>(conv_w, conv_b, gamma, beta,
                                               mean, var, proj_w);

    // 1) conv as implicit GEMM (single-term fp16, sw-pipelined)
    {
        dim3 grid(W/16, H/8, NF);
        conv_mma_kernel<<<grid, 256, CV_SMEM_BYTES>>>(x, mask, patches);
    }

    // 2) projection GEMM + bias + GELU (fp16 m16n8k16, 32x48 warp tile)
    {
        dim3 grid(DIM/GBN, M_TOK/GBM);   // (8, 64)
        gemm_tokens_f16_kernel<<<grid, 256, GEMM_SMEM_BYTES>>>(proj_b, tokens);
    }
}